// round 14
// baseline (speedup 1.0000x reference)
#include <cuda_runtime.h>
#include <cuda_bf16.h>
#include <cuda_fp16.h>
#include <cstdint>

// Problem constants
#define LQ 1024
#define SQ 1024
#define NBATCH 8
#define EDIM 512
#define BHEADS 64   // NBATCH * HHEADS

// ---------------- scratch (device globals; no allocations allowed) ----------
__device__ __half g_qph[LQ * NBATCH * EDIM];        // q proj fp16 hi plane
__device__ __half g_qpl[LQ * NBATCH * EDIM];        // q proj fp16 lo plane
__device__ __half g_kp[SQ * NBATCH * EDIM];         // k proj fp16
__device__ __half g_vp[SQ * NBATCH * EDIM];         // v proj fp16
__device__ __half g_P[67108864];                    // pos-score term fp16 (b,l,s)
__device__ __half g_E[67108864];                    // exp scores fp16 (b,l,s)
__device__ float  g_Z[BHEADS * LQ];                 // row sums
__device__ float  g_O[LQ * NBATCH * EDIM];          // content numerator fp32 (l, b*64+d)
__device__ float  g_PV[LQ * NBATCH * EDIM];         // pos-value numerator fp32
__device__ __half g_oph[LQ * NBATCH * EDIM];        // normalized O fp16 hi plane
__device__ __half g_opl[LQ * NBATCH * EDIM];        // normalized O fp16 lo plane

// =================== helpers ================================================
__device__ __forceinline__ uint32_t smem_u32(const void* p) {
    uint32_t a;
    asm("{ .reg .u64 t; cvta.to.shared.u64 t, %1; cvt.u32.u64 %0, t; }" : "=r"(a) : "l"(p));
    return a;
}
__device__ __forceinline__ void ldsm_x4(uint32_t* r, uint32_t addr) {
    asm volatile("ldmatrix.sync.aligned.m8n8.x4.shared.b16 {%0,%1,%2,%3}, [%4];"
        : "=r"(r[0]), "=r"(r[1]), "=r"(r[2]), "=r"(r[3]) : "r"(addr));
}
__device__ __forceinline__ void mma_f16(float* c, const uint32_t* a, const uint32_t* b) {
    asm volatile(
        "mma.sync.aligned.m16n8k16.row.col.f32.f16.f16.f32 "
        "{%0,%1,%2,%3}, {%4,%5,%6,%7}, {%8,%9}, {%0,%1,%2,%3};"
        : "+f"(c[0]), "+f"(c[1]), "+f"(c[2]), "+f"(c[3])
        : "r"(a[0]), "r"(a[1]), "r"(a[2]), "r"(a[3]), "r"(b[0]), "r"(b[1]));
}
// fp32 pair -> fp16 (hi, lo) packed splits
__device__ __forceinline__ void split2h(float x, float y, uint32_t& hi, uint32_t& lo) {
    __half h0 = __float2half_rn(x);
    __half h1 = __float2half_rn(y);
    __half l0 = __float2half_rn(x - __half2float(h0));
    __half l1 = __float2half_rn(y - __half2float(h1));
    hi = (uint32_t)__half_as_ushort(h0) | ((uint32_t)__half_as_ushort(h1) << 16);
    lo = (uint32_t)__half_as_ushort(l0) | ((uint32_t)__half_as_ushort(l1) << 16);
}
__device__ __forceinline__ uint32_t hi2h(float x, float y) {
    __half2 h2 = __floats2half2_rn(x, y);
    return *reinterpret_cast<uint32_t*>(&h2);
}

// =================== HMMA strided batched GEMM (fp16) ========================
// (identical to R12/R13 kernel)
template<int BM, int BN, bool BKFAST, int EPI, bool ASRC16, bool ASPLIT,
         bool BSRC16, bool BSPLIT>
__global__ __launch_bounds__(256, 2)
void mma_gemm(const void* __restrict__ Ap, const void* __restrict__ Ap2,
              long long aBS, long long aRS,
              const void* __restrict__ Bp, long long bBS, long long bS,
              void* __restrict__ Cp, void* __restrict__ Cp2,
              long long cBS, long long cRS,
              const void* __restrict__ Cin,
              const float* __restrict__ bias, float alpha,
              int K, float* __restrict__ Zp)
{
    constexpr int MT    = BM / 64;
    constexpr int NTL   = BN / 16;
    constexpr int NPAIR = NTL / 2;
    constexpr int ROWB  = 144;
    constexpr int STG   = (BM + BN) * ROWB;
    constexpr int AREG  = BM * 16 / 256;
    constexpr int BREG2 = BKFAST ? BN * 16 / 256 : 1;
    constexpr int BREG1 = BKFAST ? 1 : BN * 32 / 256;

    extern __shared__ __align__(16) char smem[];

    const int tid  = threadIdx.x;
    const int wid  = tid >> 5;
    const int lane = tid & 31;
    const int wm   = wid >> 1;
    const int wn   = wid & 1;
    const int mat  = lane >> 3;
    const int rw   = lane & 7;

    const int tile_n = blockIdx.x * BN;
    const int tile_m = blockIdx.y * BM;
    const int z      = blockIdx.z;

    const long long aOff = (long long)z * aBS + (long long)tile_m * aRS;
    const float*    AzF  = (const float*)Ap + aOff;
    const uint16_t* AzU  = (const uint16_t*)Ap + aOff;
    const uint16_t* AzU2 = (const uint16_t*)Ap2 + aOff;
    const float*    BzF  = (const float*)Bp + (long long)z * bBS;
    const uint16_t* BzU  = (const uint16_t*)Bp + (long long)z * bBS;

    float acc[MT][NTL][4];
#pragma unroll
    for (int i = 0; i < MT; i++)
#pragma unroll
        for (int j = 0; j < NTL; j++)
#pragma unroll
            for (int q = 0; q < 4; q++) acc[i][j][q] = 0.0f;

    const uint32_t s_u = smem_u32(smem);
    const uint32_t aAddr0 = s_u + (uint32_t)(wm * (BM / 4) + rw + (mat & 1) * 8) * ROWB
                                + (uint32_t)((mat >> 1) * 16);
    const uint32_t bAddr0 = s_u + (uint32_t)(BM * ROWB)
                                + (uint32_t)(wn * (BN / 2) + rw + (mat >> 1) * 8) * ROWB
                                + (uint32_t)((mat & 1) * 16);

    float2   aRegF[(!ASRC16) ? AREG : 1];
    uint32_t aRegH[ASRC16 ? AREG : 1];
    uint32_t aRegL[(ASRC16 && ASPLIT) ? AREG : 1];
    float2   bRegF[(BKFAST && !BSRC16) ? BREG2 : 1];
    uint32_t bRegH[(BKFAST && BSRC16) ? BREG2 : 1];
    float    bReg1[(!BKFAST && !BSRC16) ? BREG1 : 1];
    uint16_t bReg1U[(!BKFAST && BSRC16) ? BREG1 : 1];

    auto ldgA = [&](int ch) {
#pragma unroll
        for (int j = 0; j < AREG; j++) {
            int i = tid + j * 256;
            int k2 = i & 15, r = i >> 4;
            long long off = (long long)r * aRS + (ch << 5) + k2 * 2;
            if (ASRC16) {
                aRegH[j] = *reinterpret_cast<const uint32_t*>(AzU + off);
                if (ASPLIT)
                    aRegL[j] = *reinterpret_cast<const uint32_t*>(AzU2 + off);
            } else {
                aRegF[j] = *reinterpret_cast<const float2*>(AzF + off);
            }
        }
    };
    auto stsA = [&](int st) {
        char* base = smem + st * STG;
#pragma unroll
        for (int j = 0; j < AREG; j++) {
            int i = tid + j * 256;
            int k2 = i & 15, r = i >> 4;
            char* rp = base + r * ROWB + k2 * 4;
            if (ASRC16) {
                *reinterpret_cast<uint32_t*>(rp) = aRegH[j];
                if (ASPLIT) *reinterpret_cast<uint32_t*>(rp + 64) = aRegL[j];
            } else if (ASPLIT) {
                uint32_t hi, lo;
                split2h(aRegF[j].x, aRegF[j].y, hi, lo);
                *reinterpret_cast<uint32_t*>(rp)      = hi;
                *reinterpret_cast<uint32_t*>(rp + 64) = lo;
            } else {
                *reinterpret_cast<uint32_t*>(rp) = hi2h(aRegF[j].x, aRegF[j].y);
            }
        }
    };
    auto ldgB = [&](int ch) {
        if (BKFAST) {
#pragma unroll
            for (int j = 0; j < BREG2; j++) {
                int i = tid + j * 256;
                int k2 = i & 15, r = i >> 4;
                long long off = (long long)(tile_n + r) * bS + (ch << 5) + k2 * 2;
                if (BSRC16) bRegH[j] = *reinterpret_cast<const uint32_t*>(BzU + off);
                else        bRegF[j] = *reinterpret_cast<const float2*>(BzF + off);
            }
        } else {
#pragma unroll
            for (int j = 0; j < BREG1; j++) {
                int i = tid + j * 256;
                int n = i & (BN - 1), k = i / BN;
                long long off = (long long)((ch << 5) + k) * bS + tile_n + n;
                if (BSRC16) bReg1U[j] = BzU[off];
                else        bReg1[j]  = BzF[off];
            }
        }
    };
    auto stsB = [&](int st) {
        char* base = smem + st * STG + BM * ROWB;
        if (BKFAST) {
#pragma unroll
            for (int j = 0; j < BREG2; j++) {
                int i = tid + j * 256;
                int k2 = i & 15, r = i >> 4;
                char* rp = base + r * ROWB + k2 * 4;
                if (BSRC16) {
                    *reinterpret_cast<uint32_t*>(rp) = bRegH[j];
                } else if (BSPLIT) {
                    uint32_t hi, lo;
                    split2h(bRegF[j].x, bRegF[j].y, hi, lo);
                    *reinterpret_cast<uint32_t*>(rp)      = hi;
                    *reinterpret_cast<uint32_t*>(rp + 64) = lo;
                } else {
                    *reinterpret_cast<uint32_t*>(rp) = hi2h(bRegF[j].x, bRegF[j].y);
                }
            }
        } else {
#pragma unroll
            for (int j = 0; j < BREG1; j++) {
                int i = tid + j * 256;
                int n = i & (BN - 1), k = i / BN;
                char* rp = base + n * ROWB + k * 2;
                if (BSRC16) {
                    *reinterpret_cast<unsigned short*>(rp) = bReg1U[j];
                } else {
                    float v = bReg1[j];
                    __half hh = __float2half_rn(v);
                    *reinterpret_cast<unsigned short*>(rp) = __half_as_ushort(hh);
                    if (BSPLIT) {
                        __half ll = __float2half_rn(v - __half2float(hh));
                        *reinterpret_cast<unsigned short*>(rp + 64) = __half_as_ushort(ll);
                    }
                }
            }
        }
    };
    auto compute = [&](int st) {
        const uint32_t off = (uint32_t)(st * STG);
#pragma unroll
        for (int ks = 0; ks < 2; ks++) {
            uint32_t aH[MT][4], aL[MT][4];
#pragma unroll
            for (int mt = 0; mt < MT; mt++) {
                uint32_t ad = aAddr0 + off + (uint32_t)(mt * 16 * ROWB) + (uint32_t)(ks * 32);
                ldsm_x4(aH[mt], ad);
                if (ASPLIT) ldsm_x4(aL[mt], ad + 64);
            }
            uint32_t bH[NTL][2], bL[NTL][2];
#pragma unroll
            for (int p = 0; p < NPAIR; p++) {
                uint32_t bd = bAddr0 + off + (uint32_t)(p * 16 * ROWB) + (uint32_t)(ks * 32);
                uint32_t t[4];
                ldsm_x4(t, bd);
                bH[2 * p][0] = t[0]; bH[2 * p][1] = t[1];
                bH[2 * p + 1][0] = t[2]; bH[2 * p + 1][1] = t[3];
                if (BSPLIT) {
                    ldsm_x4(t, bd + 64);
                    bL[2 * p][0] = t[0]; bL[2 * p][1] = t[1];
                    bL[2 * p + 1][0] = t[2]; bL[2 * p + 1][1] = t[3];
                }
            }
#pragma unroll
            for (int mt = 0; mt < MT; mt++)
#pragma unroll
                for (int nt = 0; nt < NTL; nt++) {
                    mma_f16(acc[mt][nt], aH[mt], bH[nt]);
                    if (BSPLIT) mma_f16(acc[mt][nt], aH[mt], bL[nt]);
                    if (ASPLIT) mma_f16(acc[mt][nt], aL[mt], bH[nt]);
                }
        }
    };

    const int nch = K >> 5;
    ldgA(0); ldgB(0);
    stsA(0); stsB(0);
    __syncthreads();
    for (int ch = 0; ch < nch; ch++) {
        const bool more = (ch + 1 < nch);
        if (more) { ldgA(ch + 1); ldgB(ch + 1); }
        compute(ch & 1);
        if (more) {
            stsA((ch + 1) & 1); stsB((ch + 1) & 1);
            __syncthreads();
        }
    }

    // ---- epilogue ----
#pragma unroll
    for (int mt = 0; mt < MT; mt++) {
        int m0 = tile_m + wm * (BM / 4) + mt * 16 + (lane >> 2);
#pragma unroll
        for (int half = 0; half < 2; half++) {
            int m = m0 + half * 8;
            const long long coff = (long long)z * cBS + (long long)m * cRS;
            if (EPI == 6) {
                const __half* cinrow = (const __half*)Cin + coff;
                __half* erow = (__half*)Cp + coff;
                float rowsum = 0.0f;
#pragma unroll
                for (int nt = 0; nt < NTL; nt++) {
                    int n = tile_n + wn * (BN / 2) + nt * 8 + (lane & 3) * 2;
                    float2 o = __half22float2(*reinterpret_cast<const __half2*>(cinrow + n));
                    float ex = __expf(acc[mt][nt][half * 2]     + o.x);
                    float ey = __expf(acc[mt][nt][half * 2 + 1] + o.y);
                    *reinterpret_cast<__half2*>(erow + n) = __floats2half2_rn(ex, ey);
                    rowsum += ex + ey;
                }
                rowsum += __shfl_xor_sync(0xffffffffu, rowsum, 1);
                rowsum += __shfl_xor_sync(0xffffffffu, rowsum, 2);
                if ((lane & 3) == 0)
                    atomicAdd(&Zp[(long long)z * 1024 + m], rowsum);
            } else if (EPI == 7) {
                __half* crow = (__half*)Cp + coff;
#pragma unroll
                for (int nt = 0; nt < NTL; nt++) {
                    int n = tile_n + wn * (BN / 2) + nt * 8 + (lane & 3) * 2;
                    float vx = acc[mt][nt][half * 2];
                    float vy = acc[mt][nt][half * 2 + 1];
                    if (bias) { vx += bias[n]; vy += bias[n + 1]; }
                    vx *= alpha; vy *= alpha;
                    *reinterpret_cast<__half2*>(crow + n) = __floats2half2_rn(vx, vy);
                }
            } else if (EPI == 9) {
                uint16_t* crowH = (uint16_t*)Cp  + coff;
                uint16_t* crowL = (uint16_t*)Cp2 + coff;
#pragma unroll
                for (int nt = 0; nt < NTL; nt++) {
                    int n = tile_n + wn * (BN / 2) + nt * 8 + (lane & 3) * 2;
                    float vx = acc[mt][nt][half * 2];
                    float vy = acc[mt][nt][half * 2 + 1];
                    if (bias) { vx += bias[n]; vy += bias[n + 1]; }
                    vx *= alpha; vy *= alpha;
                    uint32_t hi, lo;
                    split2h(vx, vy, hi, lo);
                    *reinterpret_cast<uint32_t*>(crowH + n) = hi;
                    *reinterpret_cast<uint32_t*>(crowL + n) = lo;
                }
            } else {
                float* crow = (float*)Cp + coff;
#pragma unroll
                for (int nt = 0; nt < NTL; nt++) {
                    int n = tile_n + wn * (BN / 2) + nt * 8 + (lane & 3) * 2;
                    float vx = acc[mt][nt][half * 2];
                    float vy = acc[mt][nt][half * 2 + 1];
                    if (bias) { vx += bias[n]; vy += bias[n + 1]; }
                    vx *= alpha; vy *= alpha;
                    float2 v; v.x = vx; v.y = vy;
                    *reinterpret_cast<float2*>(crow + n) = v;
                }
            }
        }
    }
}

// =================== small kernels ===========================================
__global__ __launch_bounds__(256)
void zeroZ_kernel(float* __restrict__ Z)
{
    Z[blockIdx.x * 256 + threadIdx.x] = 0.0f;
}

// oph/opl = fp16 split of (O + PV) / Z, layout (l, b*64+d)
__global__ __launch_bounds__(256)
void merge_kernel(const float* __restrict__ O, const float* __restrict__ PV,
                  const float* __restrict__ Z,
                  __half* __restrict__ oh, __half* __restrict__ ol)
{
    int idx = (blockIdx.x * 256 + threadIdx.x) * 4;
    int l = idx >> 12;
    int b = (idx >> 6) & 63;
    float invZ = 1.0f / Z[b * 1024 + l];
    float4 o = *reinterpret_cast<const float4*>(O + idx);
    float4 p = *reinterpret_cast<const float4*>(PV + idx);
    float vx = (o.x + p.x) * invZ, vy = (o.y + p.y) * invZ;
    float vz = (o.z + p.z) * invZ, vw = (o.w + p.w) * invZ;
    uint32_t h0, l0, h1, l1;
    split2h(vx, vy, h0, l0);
    split2h(vz, vw, h1, l1);
    uint2 hv; hv.x = h0; hv.y = h1;
    uint2 lv; lv.x = l0; lv.y = l1;
    *reinterpret_cast<uint2*>(oh + idx) = hv;
    *reinterpret_cast<uint2*>(ol + idx) = lv;
}

__global__ __launch_bounds__(256)
void avgw_kernel(const __half* __restrict__ Ebuf, const float* __restrict__ Z,
                 float* __restrict__ out)
{
    int l = blockIdx.x;
    int n = blockIdx.y;
    __shared__ float invZ[8];
    if (threadIdx.x < 8)
        invZ[threadIdx.x] = 0.125f / Z[(n * 8 + threadIdx.x) * 1024 + l];
    __syncthreads();
    int s = threadIdx.x * 4;
    float4 acc = make_float4(0.f, 0.f, 0.f, 0.f);
#pragma unroll
    for (int h = 0; h < 8; h++) {
        const __half2* p = reinterpret_cast<const __half2*>(
            Ebuf + (((long long)(n * 8 + h)) << 20) + (long long)l * 1024 + s);
        float2 a = __half22float2(p[0]);
        float2 b = __half22float2(p[1]);
        float w = invZ[h];
        acc.x += a.x * w; acc.y += a.y * w; acc.z += b.x * w; acc.w += b.y * w;
    }
    *reinterpret_cast<float4*>(
        out + (((long long)n) << 20) + (long long)l * 1024 + s) = acc;
}

// =================== launch ==================================================
extern "C" void kernel_launch(void* const* d_in, const int* in_sizes, int n_in,
                              void* d_out, int out_size)
{
    const float* query = (const float*)d_in[0];
    const float* key   = (const float*)d_in[1];
    const float* value = (const float*)d_in[2];
    const float* pos_k = (const float*)d_in[3];
    const float* pos_v = (const float*)d_in[4];
    const float* Wq = (const float*)d_in[5];
    const float* bq = (const float*)d_in[6];
    const float* Wk = (const float*)d_in[7];
    const float* bk = (const float*)d_in[8];
    const float* Wv = (const float*)d_in[9];
    const float* bv = (const float*)d_in[10];
    const float* Wo = (const float*)d_in[11];
    const float* bo = (const float*)d_in[12];
    float* out = (float*)d_out;

    __half *qph, *qpl, *kp, *vp, *Pbuf, *Ebuf, *oph, *opl;
    float *Zbuf, *Obuf, *PVbuf;
    cudaGetSymbolAddress((void**)&qph,   g_qph);
    cudaGetSymbolAddress((void**)&qpl,   g_qpl);
    cudaGetSymbolAddress((void**)&kp,    g_kp);
    cudaGetSymbolAddress((void**)&vp,    g_vp);
    cudaGetSymbolAddress((void**)&Pbuf,  g_P);
    cudaGetSymbolAddress((void**)&Ebuf,  g_E);
    cudaGetSymbolAddress((void**)&Zbuf,  g_Z);
    cudaGetSymbolAddress((void**)&Obuf,  g_O);
    cudaGetSymbolAddress((void**)&PVbuf, g_PV);
    cudaGetSymbolAddress((void**)&oph,   g_oph);
    cudaGetSymbolAddress((void**)&opl,   g_opl);

    const int SM_128_64 = 2 * (128 + 64) * 144;   // 55296
    const int SM_64_128 = 2 * (64 + 128) * 144;   // 55296
    const int SM_64_64  = 2 * (64 + 64) * 144;    // 36864

    cudaFuncSetAttribute(
        (const void*)mma_gemm<128, 64, true, 9, false, true, false, false>,
        cudaFuncAttributeMaxDynamicSharedMemorySize, SM_128_64);
    cudaFuncSetAttribute(
        (const void*)mma_gemm<128, 64, true, 7, false, true, false, false>,
        cudaFuncAttributeMaxDynamicSharedMemorySize, SM_128_64);
    cudaFuncSetAttribute(
        (const void*)mma_gemm<64, 128, true, 7, true, false, false, false>,
        cudaFuncAttributeMaxDynamicSharedMemorySize, SM_64_128);
    cudaFuncSetAttribute(
        (const void*)mma_gemm<128, 64, true, 6, true, true, true, false>,
        cudaFuncAttributeMaxDynamicSharedMemorySize, SM_128_64);
    cudaFuncSetAttribute(
        (const void*)mma_gemm<128, 64, false, 0, true, false, true, false>,
        cudaFuncAttributeMaxDynamicSharedMemorySize, SM_128_64);
    cudaFuncSetAttribute(
        (const void*)mma_gemm<64, 64, false, 0, true, false, false, false>,
        cudaFuncAttributeMaxDynamicSharedMemorySize, SM_64_64);
    cudaFuncSetAttribute(
        (const void*)mma_gemm<128, 64, true, 0, true, true, false, false>,
        cudaFuncAttributeMaxDynamicSharedMemorySize, SM_128_64);

    // ---- side streams + events (created once, before any capture) ----
    static cudaStream_t sB = nullptr, sC = nullptr;
    static cudaEvent_t evStart, evB1, evC1, evScores, evPV, evAvgw;
    if (sB == nullptr) {
        cudaStreamCreateWithFlags(&sB, cudaStreamNonBlocking);
        cudaStreamCreateWithFlags(&sC, cudaStreamNonBlocking);
        cudaEventCreateWithFlags(&evStart,  cudaEventDisableTiming);
        cudaEventCreateWithFlags(&evB1,     cudaEventDisableTiming);
        cudaEventCreateWithFlags(&evC1,     cudaEventDisableTiming);
        cudaEventCreateWithFlags(&evScores, cudaEventDisableTiming);
        cudaEventCreateWithFlags(&evPV,     cudaEventDisableTiming);
        cudaEventCreateWithFlags(&evAvgw,   cudaEventDisableTiming);
    }

    // fork side streams from the (captured) main stream
    cudaEventRecord(evStart, 0);
    cudaStreamWaitEvent(sB, evStart, 0);
    cudaStreamWaitEvent(sC, evStart, 0);

    // --- stream B: zeroZ + proj k; later avgw ---
    zeroZ_kernel<<<256, 256, 0, sB>>>(Zbuf);
    mma_gemm<128, 64, true, 7, false, true, false, false>
        <<<dim3(8, 64, 1), 256, SM_128_64, sB>>>(
        key, nullptr, 0, 512,  Wk, 0, 512,
        kp, nullptr, 0, 512,  nullptr, bk, 1.0f, 512, nullptr);
    cudaEventRecord(evB1, sB);

    // --- stream C: proj v; later posvN ---
    mma_gemm<128, 64, true, 7, false, true, false, false>
        <<<dim3(8, 64, 1), 256, SM_128_64, sC>>>(
        value, nullptr, 0, 512,  Wv, 0, 512,
        vp, nullptr, 0, 512,  nullptr, bv, 1.0f, 512, nullptr);
    cudaEventRecord(evC1, sC);

    // --- main: proj q -> posk ---
    mma_gemm<128, 64, true, 9, false, true, false, false>
        <<<dim3(8, 64, 1), 256, SM_128_64>>>(
        query, nullptr, 0, 512,  Wq, 0, 512,
        qph, qpl, 0, 512,  nullptr, bq, 0.125f, 512, nullptr);

    mma_gemm<64, 128, true, 7, true, false, false, false>
        <<<dim3(8, 1, 1024), 256, SM_64_128>>>(
        qph, nullptr, 4096, 64,  pos_k, 65536, 64,
        Pbuf, nullptr, 1024, (long long)1 << 20,
        nullptr, nullptr, 1.0f, 64, nullptr);

    // --- main: scores (needs proj k + zeroZ from stream B) ---
    cudaStreamWaitEvent(0, evB1, 0);
    mma_gemm<128, 64, true, 6, true, true, true, false>
        <<<dim3(16, 8, 64), 256, SM_128_64>>>(
        qph, qpl, 64, 4096,  kp, 64, 4096,
        Ebuf, nullptr, (long long)1 << 20, 1024,
        Pbuf, nullptr, 1.0f, 64, Zbuf);
    cudaEventRecord(evScores, 0);

    // --- stream B: avgw (needs E + Z; overlaps contout/posvN) ---
    cudaStreamWaitEvent(sB, evScores, 0);
    avgw_kernel<<<dim3(1024, 8, 1), 256, 0, sB>>>(Ebuf, Zbuf, out + 4194304);
    cudaEventRecord(evAvgw, sB);

    // --- stream C: posvN = E @ pos_v -> PV fp32 (concurrent with contout) ---
    cudaStreamWaitEvent(sC, evScores, 0);
    mma_gemm<64, 64, false, 0, true, false, false, false>
        <<<dim3(1, 1, 1024), 256, SM_64_64, sC>>>(
        Ebuf, nullptr, 1024, (long long)1 << 20,  pos_v, 65536, 64,
        PVbuf, nullptr, 4096, 64,  nullptr, nullptr, 1.0f, 1024, nullptr);
    cudaEventRecord(evPV, sC);

    // --- main: contout = E @ v -> O fp32 (needs proj v) ---
    cudaStreamWaitEvent(0, evC1, 0);
    mma_gemm<128, 64, false, 0, true, false, true, false>
        <<<dim3(1, 8, 64), 256, SM_128_64>>>(
        Ebuf, nullptr, (long long)1 << 20, 1024,  vp, 64, 4096,
        Obuf, nullptr, 64, 4096,  nullptr, nullptr, 1.0f, 1024, nullptr);

    // --- main: merge (O + PV)/Z -> planar fp16 ---
    cudaStreamWaitEvent(0, evPV, 0);
    merge_kernel<<<4096, 256>>>(Obuf, PVbuf, Zbuf, oph, opl);

    // --- main: output projection ---
    mma_gemm<128, 64, true, 0, true, true, false, false>
        <<<dim3(8, 64, 1), 256, SM_128_64>>>(
        oph, opl, 0, 512,  Wo, 0, 512,
        out, nullptr, 0, 512,  nullptr, bo, 1.0f, 512, nullptr);

    // join stream B (avgw) back into main before capture ends
    cudaStreamWaitEvent(0, evAvgw, 0);
}

// round 15
// speedup vs baseline: 1.0723x; 1.0723x over previous
#include <cuda_runtime.h>
#include <cuda_bf16.h>
#include <cuda_fp16.h>
#include <cstdint>

// Problem constants
#define LQ 1024
#define SQ 1024
#define NBATCH 8
#define EDIM 512
#define BHEADS 64   // NBATCH * HHEADS

// ---------------- scratch (device globals; no allocations allowed) ----------
__device__ __half g_qp[LQ * NBATCH * EDIM];         // q proj fp16
__device__ __half g_kp[SQ * NBATCH * EDIM];         // k proj fp16
__device__ __half g_vp[SQ * NBATCH * EDIM];         // v proj fp16
__device__ __half g_P[67108864];                    // pos-score term fp16 (b,l,s)
__device__ __half g_E[67108864];                    // exp scores fp16 (b,l,s)
__device__ float  g_Z[BHEADS * LQ];                 // row sums
__device__ float  g_O[LQ * NBATCH * EDIM];          // content numerator fp32 (l, b*64+d)
__device__ __half g_oph[LQ * NBATCH * EDIM];        // normalized O fp16

// =================== helpers ================================================
__device__ __forceinline__ uint32_t smem_u32(const void* p) {
    uint32_t a;
    asm("{ .reg .u64 t; cvta.to.shared.u64 t, %1; cvt.u32.u64 %0, t; }" : "=r"(a) : "l"(p));
    return a;
}
__device__ __forceinline__ void ldsm_x4(uint32_t* r, uint32_t addr) {
    asm volatile("ldmatrix.sync.aligned.m8n8.x4.shared.b16 {%0,%1,%2,%3}, [%4];"
        : "=r"(r[0]), "=r"(r[1]), "=r"(r[2]), "=r"(r[3]) : "r"(addr));
}
__device__ __forceinline__ void mma_f16(float* c, const uint32_t* a, const uint32_t* b) {
    asm volatile(
        "mma.sync.aligned.m16n8k16.row.col.f32.f16.f16.f32 "
        "{%0,%1,%2,%3}, {%4,%5,%6,%7}, {%8,%9}, {%0,%1,%2,%3};"
        : "+f"(c[0]), "+f"(c[1]), "+f"(c[2]), "+f"(c[3])
        : "r"(a[0]), "r"(a[1]), "r"(a[2]), "r"(a[3]), "r"(b[0]), "r"(b[1]));
}
// fp32 pair -> fp16 (hi, lo) packed splits
__device__ __forceinline__ void split2h(float x, float y, uint32_t& hi, uint32_t& lo) {
    __half h0 = __float2half_rn(x);
    __half h1 = __float2half_rn(y);
    __half l0 = __float2half_rn(x - __half2float(h0));
    __half l1 = __float2half_rn(y - __half2float(h1));
    hi = (uint32_t)__half_as_ushort(h0) | ((uint32_t)__half_as_ushort(h1) << 16);
    lo = (uint32_t)__half_as_ushort(l0) | ((uint32_t)__half_as_ushort(l1) << 16);
}
__device__ __forceinline__ uint32_t hi2h(float x, float y) {
    __half2 h2 = __floats2half2_rn(x, y);
    return *reinterpret_cast<uint32_t*>(&h2);
}

// =================== HMMA strided batched GEMM (fp16) ========================
// C[z][m][n] = epilogue( sum_k A(m,k)*B(n,k) )
// A(m,k): k contiguous. ASRC16 ? fp16 planes (hi at Ap, lo at Ap2 if ASPLIT)
//                               : fp32 (fp16-split in kernel; lo used if ASPLIT)
// B: BKFAST (k contig): BSRC16 ? fp16 plane at Bp : fp32 -> fp16 (split if BSPLIT)
//    !BKFAST (n contig): BSRC16 ? fp16 plane : fp32 -> fp16 hi (BSPLIT adds lo)
// MMA terms: aH*bH  [+ aH*bL if BSPLIT]  [+ aL*bH if ASPLIT]
// EPI: 0 = fp32 C = alpha*(acc+bias)
//      6 = EXPZ: e = exp(acc + CinH[..]); fp16 e -> Cp; atomicAdd Zp[z*1024+m]
//      7 = fp16 Cp = alpha*(acc+bias)
//      8 = DIVZ: fp16 Cp = (acc + CinF)/Zp[m*1024+z]
// 256 threads = 8 warps (4m x 2n). BK=32. Double-buffered. 2 CTAs/SM.
template<int BM, int BN, bool BKFAST, int EPI, bool ASRC16, bool ASPLIT,
         bool BSRC16, bool BSPLIT>
__global__ __launch_bounds__(256, 2)
void mma_gemm(const void* __restrict__ Ap, const void* __restrict__ Ap2,
              long long aBS, long long aRS,
              const void* __restrict__ Bp, long long bBS, long long bS,
              void* __restrict__ Cp, long long cBS, long long cRS,
              const void* __restrict__ Cin,
              const float* __restrict__ bias, float alpha,
              int K, float* __restrict__ Zp)
{
    constexpr int MT    = BM / 64;
    constexpr int NTL   = BN / 16;
    constexpr int NPAIR = NTL / 2;
    constexpr int ROWB  = 144;
    constexpr int STG   = (BM + BN) * ROWB;
    constexpr int AREG  = BM * 16 / 256;
    constexpr int BREG2 = BKFAST ? BN * 16 / 256 : 1;
    constexpr int BREG1 = BKFAST ? 1 : BN * 32 / 256;

    extern __shared__ __align__(16) char smem[];

    const int tid  = threadIdx.x;
    const int wid  = tid >> 5;
    const int lane = tid & 31;
    const int wm   = wid >> 1;
    const int wn   = wid & 1;
    const int mat  = lane >> 3;
    const int rw   = lane & 7;

    const int tile_n = blockIdx.x * BN;
    const int tile_m = blockIdx.y * BM;
    const int z      = blockIdx.z;

    const long long aOff = (long long)z * aBS + (long long)tile_m * aRS;
    const float*    AzF  = (const float*)Ap + aOff;
    const uint16_t* AzU  = (const uint16_t*)Ap + aOff;
    const uint16_t* AzU2 = (const uint16_t*)Ap2 + aOff;
    const float*    BzF  = (const float*)Bp + (long long)z * bBS;
    const uint16_t* BzU  = (const uint16_t*)Bp + (long long)z * bBS;

    float acc[MT][NTL][4];
#pragma unroll
    for (int i = 0; i < MT; i++)
#pragma unroll
        for (int j = 0; j < NTL; j++)
#pragma unroll
            for (int q = 0; q < 4; q++) acc[i][j][q] = 0.0f;

    const uint32_t s_u = smem_u32(smem);
    const uint32_t aAddr0 = s_u + (uint32_t)(wm * (BM / 4) + rw + (mat & 1) * 8) * ROWB
                                + (uint32_t)((mat >> 1) * 16);
    const uint32_t bAddr0 = s_u + (uint32_t)(BM * ROWB)
                                + (uint32_t)(wn * (BN / 2) + rw + (mat >> 1) * 8) * ROWB
                                + (uint32_t)((mat & 1) * 16);

    float2   aRegF[(!ASRC16) ? AREG : 1];
    uint32_t aRegH[ASRC16 ? AREG : 1];
    uint32_t aRegL[(ASRC16 && ASPLIT) ? AREG : 1];
    float2   bRegF[(BKFAST && !BSRC16) ? BREG2 : 1];
    uint32_t bRegH[(BKFAST && BSRC16) ? BREG2 : 1];
    float    bReg1[(!BKFAST && !BSRC16) ? BREG1 : 1];
    uint16_t bReg1U[(!BKFAST && BSRC16) ? BREG1 : 1];

    auto ldgA = [&](int ch) {
#pragma unroll
        for (int j = 0; j < AREG; j++) {
            int i = tid + j * 256;
            int k2 = i & 15, r = i >> 4;
            long long off = (long long)r * aRS + (ch << 5) + k2 * 2;
            if (ASRC16) {
                aRegH[j] = *reinterpret_cast<const uint32_t*>(AzU + off);
                if (ASPLIT)
                    aRegL[j] = *reinterpret_cast<const uint32_t*>(AzU2 + off);
            } else {
                aRegF[j] = *reinterpret_cast<const float2*>(AzF + off);
            }
        }
    };
    auto stsA = [&](int st) {
        char* base = smem + st * STG;
#pragma unroll
        for (int j = 0; j < AREG; j++) {
            int i = tid + j * 256;
            int k2 = i & 15, r = i >> 4;
            char* rp = base + r * ROWB + k2 * 4;
            if (ASRC16) {
                *reinterpret_cast<uint32_t*>(rp) = aRegH[j];
                if (ASPLIT) *reinterpret_cast<uint32_t*>(rp + 64) = aRegL[j];
            } else if (ASPLIT) {
                uint32_t hi, lo;
                split2h(aRegF[j].x, aRegF[j].y, hi, lo);
                *reinterpret_cast<uint32_t*>(rp)      = hi;
                *reinterpret_cast<uint32_t*>(rp + 64) = lo;
            } else {
                *reinterpret_cast<uint32_t*>(rp) = hi2h(aRegF[j].x, aRegF[j].y);
            }
        }
    };
    auto ldgB = [&](int ch) {
        if (BKFAST) {
#pragma unroll
            for (int j = 0; j < BREG2; j++) {
                int i = tid + j * 256;
                int k2 = i & 15, r = i >> 4;
                long long off = (long long)(tile_n + r) * bS + (ch << 5) + k2 * 2;
                if (BSRC16) bRegH[j] = *reinterpret_cast<const uint32_t*>(BzU + off);
                else        bRegF[j] = *reinterpret_cast<const float2*>(BzF + off);
            }
        } else {
#pragma unroll
            for (int j = 0; j < BREG1; j++) {
                int i = tid + j * 256;
                int n = i & (BN - 1), k = i / BN;
                long long off = (long long)((ch << 5) + k) * bS + tile_n + n;
                if (BSRC16) bReg1U[j] = BzU[off];
                else        bReg1[j]  = BzF[off];
            }
        }
    };
    auto stsB = [&](int st) {
        char* base = smem + st * STG + BM * ROWB;
        if (BKFAST) {
#pragma unroll
            for (int j = 0; j < BREG2; j++) {
                int i = tid + j * 256;
                int k2 = i & 15, r = i >> 4;
                char* rp = base + r * ROWB + k2 * 4;
                if (BSRC16) {
                    *reinterpret_cast<uint32_t*>(rp) = bRegH[j];
                } else if (BSPLIT) {
                    uint32_t hi, lo;
                    split2h(bRegF[j].x, bRegF[j].y, hi, lo);
                    *reinterpret_cast<uint32_t*>(rp)      = hi;
                    *reinterpret_cast<uint32_t*>(rp + 64) = lo;
                } else {
                    *reinterpret_cast<uint32_t*>(rp) = hi2h(bRegF[j].x, bRegF[j].y);
                }
            }
        } else {
#pragma unroll
            for (int j = 0; j < BREG1; j++) {
                int i = tid + j * 256;
                int n = i & (BN - 1), k = i / BN;
                char* rp = base + n * ROWB + k * 2;
                if (BSRC16) {
                    *reinterpret_cast<unsigned short*>(rp) = bReg1U[j];
                } else {
                    float v = bReg1[j];
                    __half hh = __float2half_rn(v);
                    *reinterpret_cast<unsigned short*>(rp) = __half_as_ushort(hh);
                    if (BSPLIT) {
                        __half ll = __float2half_rn(v - __half2float(hh));
                        *reinterpret_cast<unsigned short*>(rp + 64) = __half_as_ushort(ll);
                    }
                }
            }
        }
    };
    auto compute = [&](int st) {
        const uint32_t off = (uint32_t)(st * STG);
#pragma unroll
        for (int ks = 0; ks < 2; ks++) {
            uint32_t aH[MT][4], aL[MT][4];
#pragma unroll
            for (int mt = 0; mt < MT; mt++) {
                uint32_t ad = aAddr0 + off + (uint32_t)(mt * 16 * ROWB) + (uint32_t)(ks * 32);
                ldsm_x4(aH[mt], ad);
                if (ASPLIT) ldsm_x4(aL[mt], ad + 64);
            }
            uint32_t bH[NTL][2], bL[NTL][2];
#pragma unroll
            for (int p = 0; p < NPAIR; p++) {
                uint32_t bd = bAddr0 + off + (uint32_t)(p * 16 * ROWB) + (uint32_t)(ks * 32);
                uint32_t t[4];
                ldsm_x4(t, bd);
                bH[2 * p][0] = t[0]; bH[2 * p][1] = t[1];
                bH[2 * p + 1][0] = t[2]; bH[2 * p + 1][1] = t[3];
                if (BSPLIT) {
                    ldsm_x4(t, bd + 64);
                    bL[2 * p][0] = t[0]; bL[2 * p][1] = t[1];
                    bL[2 * p + 1][0] = t[2]; bL[2 * p + 1][1] = t[3];
                }
            }
#pragma unroll
            for (int mt = 0; mt < MT; mt++)
#pragma unroll
                for (int nt = 0; nt < NTL; nt++) {
                    mma_f16(acc[mt][nt], aH[mt], bH[nt]);
                    if (BSPLIT) mma_f16(acc[mt][nt], aH[mt], bL[nt]);
                    if (ASPLIT) mma_f16(acc[mt][nt], aL[mt], bH[nt]);
                }
        }
    };

    const int nch = K >> 5;
    ldgA(0); ldgB(0);
    stsA(0); stsB(0);
    __syncthreads();
    for (int ch = 0; ch < nch; ch++) {
        const bool more = (ch + 1 < nch);
        if (more) { ldgA(ch + 1); ldgB(ch + 1); }
        compute(ch & 1);
        if (more) {
            stsA((ch + 1) & 1); stsB((ch + 1) & 1);
            __syncthreads();
        }
    }

    // ---- epilogue ----
#pragma unroll
    for (int mt = 0; mt < MT; mt++) {
        int m0 = tile_m + wm * (BM / 4) + mt * 16 + (lane >> 2);
#pragma unroll
        for (int half = 0; half < 2; half++) {
            int m = m0 + half * 8;
            const long long coff = (long long)z * cBS + (long long)m * cRS;
            if (EPI == 6) {
                const __half* cinrow = (const __half*)Cin + coff;
                __half* erow = (__half*)Cp + coff;
                float rowsum = 0.0f;
#pragma unroll
                for (int nt = 0; nt < NTL; nt++) {
                    int n = tile_n + wn * (BN / 2) + nt * 8 + (lane & 3) * 2;
                    float2 o = __half22float2(*reinterpret_cast<const __half2*>(cinrow + n));
                    float ex = __expf(acc[mt][nt][half * 2]     + o.x);
                    float ey = __expf(acc[mt][nt][half * 2 + 1] + o.y);
                    *reinterpret_cast<__half2*>(erow + n) = __floats2half2_rn(ex, ey);
                    rowsum += ex + ey;
                }
                rowsum += __shfl_xor_sync(0xffffffffu, rowsum, 1);
                rowsum += __shfl_xor_sync(0xffffffffu, rowsum, 2);
                if ((lane & 3) == 0)
                    atomicAdd(&Zp[(long long)z * 1024 + m], rowsum);
            } else if (EPI == 7) {
                __half* crow = (__half*)Cp + coff;
#pragma unroll
                for (int nt = 0; nt < NTL; nt++) {
                    int n = tile_n + wn * (BN / 2) + nt * 8 + (lane & 3) * 2;
                    float vx = acc[mt][nt][half * 2];
                    float vy = acc[mt][nt][half * 2 + 1];
                    if (bias) { vx += bias[n]; vy += bias[n + 1]; }
                    vx *= alpha; vy *= alpha;
                    *reinterpret_cast<__half2*>(crow + n) = __floats2half2_rn(vx, vy);
                }
            } else if (EPI == 8) {
                const float* cinrow = (const float*)Cin + coff;
                __half* crow = (__half*)Cp + coff;
                float invZ = 1.0f / Zp[(long long)m * 1024 + z];
#pragma unroll
                for (int nt = 0; nt < NTL; nt++) {
                    int n = tile_n + wn * (BN / 2) + nt * 8 + (lane & 3) * 2;
                    float2 o = *reinterpret_cast<const float2*>(cinrow + n);
                    float vx = (acc[mt][nt][half * 2]     + o.x) * invZ;
                    float vy = (acc[mt][nt][half * 2 + 1] + o.y) * invZ;
                    *reinterpret_cast<__half2*>(crow + n) = __floats2half2_rn(vx, vy);
                }
            } else {
                float* crow = (float*)Cp + coff;
#pragma unroll
                for (int nt = 0; nt < NTL; nt++) {
                    int n = tile_n + wn * (BN / 2) + nt * 8 + (lane & 3) * 2;
                    float vx = acc[mt][nt][half * 2];
                    float vy = acc[mt][nt][half * 2 + 1];
                    if (bias) { vx += bias[n]; vy += bias[n + 1]; }
                    vx *= alpha; vy *= alpha;
                    float2 v; v.x = vx; v.y = vy;
                    *reinterpret_cast<float2*>(crow + n) = v;
                }
            }
        }
    }
}

// =================== small kernels ===========================================
__global__ __launch_bounds__(256)
void zeroZ_kernel(float* __restrict__ Z)
{
    Z[blockIdx.x * 256 + threadIdx.x] = 0.0f;
}

__global__ __launch_bounds__(256)
void avgw_kernel(const __half* __restrict__ Ebuf, const float* __restrict__ Z,
                 float* __restrict__ out)
{
    int l = blockIdx.x;
    int n = blockIdx.y;
    __shared__ float invZ[8];
    if (threadIdx.x < 8)
        invZ[threadIdx.x] = 0.125f / Z[(n * 8 + threadIdx.x) * 1024 + l];
    __syncthreads();
    int s = threadIdx.x * 4;
    float4 acc = make_float4(0.f, 0.f, 0.f, 0.f);
#pragma unroll
    for (int h = 0; h < 8; h++) {
        const __half2* p = reinterpret_cast<const __half2*>(
            Ebuf + (((long long)(n * 8 + h)) << 20) + (long long)l * 1024 + s);
        float2 a = __half22float2(p[0]);
        float2 b = __half22float2(p[1]);
        float w = invZ[h];
        acc.x += a.x * w; acc.y += a.y * w; acc.z += b.x * w; acc.w += b.y * w;
    }
    *reinterpret_cast<float4*>(
        out + (((long long)n) << 20) + (long long)l * 1024 + s) = acc;
}

// =================== launch ==================================================
extern "C" void kernel_launch(void* const* d_in, const int* in_sizes, int n_in,
                              void* d_out, int out_size)
{
    const float* query = (const float*)d_in[0];
    const float* key   = (const float*)d_in[1];
    const float* value = (const float*)d_in[2];
    const float* pos_k = (const float*)d_in[3];
    const float* pos_v = (const float*)d_in[4];
    const float* Wq = (const float*)d_in[5];
    const float* bq = (const float*)d_in[6];
    const float* Wk = (const float*)d_in[7];
    const float* bk = (const float*)d_in[8];
    const float* Wv = (const float*)d_in[9];
    const float* bv = (const float*)d_in[10];
    const float* Wo = (const float*)d_in[11];
    const float* bo = (const float*)d_in[12];
    float* out = (float*)d_out;

    __half *qp, *kp, *vp, *Pbuf, *Ebuf, *oph;
    float *Zbuf, *Obuf;
    cudaGetSymbolAddress((void**)&qp,    g_qp);
    cudaGetSymbolAddress((void**)&kp,    g_kp);
    cudaGetSymbolAddress((void**)&vp,    g_vp);
    cudaGetSymbolAddress((void**)&Pbuf,  g_P);
    cudaGetSymbolAddress((void**)&Ebuf,  g_E);
    cudaGetSymbolAddress((void**)&Zbuf,  g_Z);
    cudaGetSymbolAddress((void**)&Obuf,  g_O);
    cudaGetSymbolAddress((void**)&oph,   g_oph);

    const int SM_128_64 = 2 * (128 + 64) * 144;   // 55296
    const int SM_64_128 = 2 * (64 + 128) * 144;   // 55296
    const int SM_64_64  = 2 * (64 + 64) * 144;    // 36864

    // projections (q/k/v identical instance): fp32 A 2-term, W->fp16 hi, fp16 out
    cudaFuncSetAttribute(
        (const void*)mma_gemm<128, 64, true, 7, false, true, false, false>,
        cudaFuncAttributeMaxDynamicSharedMemorySize, SM_128_64);
    // posk: A = qp fp16 (1-term), B = pos_k fp32->fp16 hi, fp16 P out
    cudaFuncSetAttribute(
        (const void*)mma_gemm<64, 128, true, 7, true, false, false, false>,
        cudaFuncAttributeMaxDynamicSharedMemorySize, SM_64_128);
    // scores: A = qp fp16 (1-term), B = kp fp16, EXPZ
    cudaFuncSetAttribute(
        (const void*)mma_gemm<128, 64, true, 6, true, false, true, false>,
        cudaFuncAttributeMaxDynamicSharedMemorySize, SM_128_64);
    // contout: A = E fp16, B = vp fp16 n-contig (1-term), fp32 out
    cudaFuncSetAttribute(
        (const void*)mma_gemm<128, 64, false, 0, true, false, true, false>,
        cudaFuncAttributeMaxDynamicSharedMemorySize, SM_128_64);
    // posv: A = E fp16, B = pos_v fp32->fp16 hi n-contig (1-term), DIVZ fp16 out
    cudaFuncSetAttribute(
        (const void*)mma_gemm<64, 64, false, 8, true, false, false, false>,
        cudaFuncAttributeMaxDynamicSharedMemorySize, SM_64_64);
    // outproj: A = oph fp16 (1-term), B = Wo fp32->fp16 hi, fp32 out
    cudaFuncSetAttribute(
        (const void*)mma_gemm<128, 64, true, 0, true, false, false, false>,
        cudaFuncAttributeMaxDynamicSharedMemorySize, SM_128_64);

    // ---- side streams + events (created once, before any capture) ----
    static cudaStream_t sB = nullptr, sC = nullptr;
    static cudaEvent_t evStart, evB1, evC1, evScores, evAvgw;
    if (sB == nullptr) {
        cudaStreamCreateWithFlags(&sB, cudaStreamNonBlocking);
        cudaStreamCreateWithFlags(&sC, cudaStreamNonBlocking);
        cudaEventCreateWithFlags(&evStart,  cudaEventDisableTiming);
        cudaEventCreateWithFlags(&evB1,     cudaEventDisableTiming);
        cudaEventCreateWithFlags(&evC1,     cudaEventDisableTiming);
        cudaEventCreateWithFlags(&evScores, cudaEventDisableTiming);
        cudaEventCreateWithFlags(&evAvgw,   cudaEventDisableTiming);
    }

    // fork side streams from the (captured) main stream
    cudaEventRecord(evStart, 0);
    cudaStreamWaitEvent(sB, evStart, 0);
    cudaStreamWaitEvent(sC, evStart, 0);

    // --- stream B: zeroZ + proj k; later avgw ---
    zeroZ_kernel<<<256, 256, 0, sB>>>(Zbuf);
    mma_gemm<128, 64, true, 7, false, true, false, false>
        <<<dim3(8, 64, 1), 256, SM_128_64, sB>>>(
        key, nullptr, 0, 512,  Wk, 0, 512,
        kp, 0, 512,  nullptr, bk, 1.0f, 512, nullptr);
    cudaEventRecord(evB1, sB);

    // --- stream C: proj v ---
    mma_gemm<128, 64, true, 7, false, true, false, false>
        <<<dim3(8, 64, 1), 256, SM_128_64, sC>>>(
        value, nullptr, 0, 512,  Wv, 0, 512,
        vp, 0, 512,  nullptr, bv, 1.0f, 512, nullptr);
    cudaEventRecord(evC1, sC);

    // --- main: proj q -> posk ---
    mma_gemm<128, 64, true, 7, false, true, false, false>
        <<<dim3(8, 64, 1), 256, SM_128_64>>>(
        query, nullptr, 0, 512,  Wq, 0, 512,
        qp, 0, 512,  nullptr, bq, 0.125f, 512, nullptr);

    mma_gemm<64, 128, true, 7, true, false, false, false>
        <<<dim3(8, 1, 1024), 256, SM_64_128>>>(
        qp, nullptr, 4096, 64,  pos_k, 65536, 64,
        Pbuf, 1024, (long long)1 << 20,
        nullptr, nullptr, 1.0f, 64, nullptr);

    // --- main: scores (needs proj k + zeroZ from stream B), 1-term ---
    cudaStreamWaitEvent(0, evB1, 0);
    mma_gemm<128, 64, true, 6, true, false, true, false>
        <<<dim3(16, 8, 64), 256, SM_128_64>>>(
        qp, nullptr, 64, 4096,  kp, 64, 4096,
        Ebuf, (long long)1 << 20, 1024,
        Pbuf, nullptr, 1.0f, 64, Zbuf);
    cudaEventRecord(evScores, 0);

    // --- stream B: avgw (overlaps contout/posv/outproj) ---
    cudaStreamWaitEvent(sB, evScores, 0);
    avgw_kernel<<<dim3(1024, 8, 1), 256, 0, sB>>>(Ebuf, Zbuf, out + 4194304);
    cudaEventRecord(evAvgw, sB);

    // --- main: contout = E @ v -> O fp32 (needs proj v) ---
    cudaStreamWaitEvent(0, evC1, 0);
    mma_gemm<128, 64, false, 0, true, false, true, false>
        <<<dim3(1, 8, 64), 256, SM_128_64>>>(
        Ebuf, nullptr, (long long)1 << 20, 1024,  vp, 64, 4096,
        Obuf, 64, 4096,  nullptr, nullptr, 1.0f, 1024, nullptr);

    // --- main: posv + normalize -> fp16 oph ---
    mma_gemm<64, 64, false, 8, true, false, false, false>
        <<<dim3(1, 1, 1024), 256, SM_64_64>>>(
        Ebuf, nullptr, 1024, (long long)1 << 20,  pos_v, 65536, 64,
        oph, 4096, 64,  Obuf, nullptr, 1.0f, 1024, Zbuf);

    // --- main: output projection (1-term) ---
    mma_gemm<128, 64, true, 0, true, false, false, false>
        <<<dim3(8, 64, 1), 256, SM_128_64>>>(
        oph, nullptr, 0, 512,  Wo, 0, 512,
        out, 0, 512,  nullptr, bo, 1.0f, 512, nullptr);

    // join stream B (avgw) back into main before capture ends
    cudaStreamWaitEvent(0, evAvgw, 0);
}

// round 16
// speedup vs baseline: 1.1428x; 1.0658x over previous
#include <cuda_runtime.h>
#include <cuda_bf16.h>
#include <cuda_fp16.h>
#include <cstdint>

// Problem constants
#define LQ 1024
#define SQ 1024
#define NBATCH 8
#define EDIM 512
#define BHEADS 64   // NBATCH * HHEADS

// ---------------- scratch (device globals; no allocations allowed) ----------
__device__ __half g_qp[LQ * NBATCH * EDIM];         // q proj fp16
__device__ __half g_kp[SQ * NBATCH * EDIM];         // k proj fp16
__device__ __half g_vp[SQ * NBATCH * EDIM];         // v proj fp16
__device__ __half g_P[67108864];                    // pos-score term fp16 (b,l,s)
__device__ __half g_E[67108864];                    // exp scores fp16 (b,l,s)
__device__ float  g_Z[BHEADS * LQ];                 // row sums
__device__ float  g_O[LQ * NBATCH * EDIM];          // content numerator fp32 (l, b*64+d)
__device__ __half g_oph[LQ * NBATCH * EDIM];        // normalized O fp16

// =================== helpers ================================================
__device__ __forceinline__ uint32_t smem_u32(const void* p) {
    uint32_t a;
    asm("{ .reg .u64 t; cvta.to.shared.u64 t, %1; cvt.u32.u64 %0, t; }" : "=r"(a) : "l"(p));
    return a;
}
__device__ __forceinline__ void ldsm_x4(uint32_t* r, uint32_t addr) {
    asm volatile("ldmatrix.sync.aligned.m8n8.x4.shared.b16 {%0,%1,%2,%3}, [%4];"
        : "=r"(r[0]), "=r"(r[1]), "=r"(r[2]), "=r"(r[3]) : "r"(addr));
}
__device__ __forceinline__ void mma_f16(float* c, const uint32_t* a, const uint32_t* b) {
    asm volatile(
        "mma.sync.aligned.m16n8k16.row.col.f32.f16.f16.f32 "
        "{%0,%1,%2,%3}, {%4,%5,%6,%7}, {%8,%9}, {%0,%1,%2,%3};"
        : "+f"(c[0]), "+f"(c[1]), "+f"(c[2]), "+f"(c[3])
        : "r"(a[0]), "r"(a[1]), "r"(a[2]), "r"(a[3]), "r"(b[0]), "r"(b[1]));
}
// fp32 pair -> fp16 (hi, lo) packed splits
__device__ __forceinline__ void split2h(float x, float y, uint32_t& hi, uint32_t& lo) {
    __half h0 = __float2half_rn(x);
    __half h1 = __float2half_rn(y);
    __half l0 = __float2half_rn(x - __half2float(h0));
    __half l1 = __float2half_rn(y - __half2float(h1));
    hi = (uint32_t)__half_as_ushort(h0) | ((uint32_t)__half_as_ushort(h1) << 16);
    lo = (uint32_t)__half_as_ushort(l0) | ((uint32_t)__half_as_ushort(l1) << 16);
}
__device__ __forceinline__ uint32_t hi2h(float x, float y) {
    __half2 h2 = __floats2half2_rn(x, y);
    return *reinterpret_cast<uint32_t*>(&h2);
}

// =================== HMMA strided batched GEMM (fp16) ========================
// C[z][m][n] = epilogue( sum_k A(m,k)*B(n,k) )
// A(m,k): k contiguous. ASRC16 ? fp16 planes (hi at Ap, lo at Ap2 if ASPLIT)
//                               : fp32 (fp16-split in kernel; lo used if ASPLIT)
// B: BKFAST (k contig): BSRC16 ? fp16 plane at Bp : fp32 -> fp16 (split if BSPLIT)
//    !BKFAST (n contig): BSRC16 ? fp16 plane : fp32 -> fp16 hi (BSPLIT adds lo)
// MMA terms: aH*bH  [+ aH*bL if BSPLIT]  [+ aL*bH if ASPLIT]
// EPI: 0 = fp32 C = alpha*(acc+bias)
//      6 = EXPZ: e = exp(acc + CinH[..]); fp16 e -> Cp; atomicAdd Zp[z*1024+m]
//      7 = fp16 Cp = alpha*(acc+bias)
//      8 = DIVZ: fp16 Cp = (acc + CinF)/Zp[m*1024+z]
// 256 threads = 8 warps (4m x 2n). BK=32. Double-buffered. 2 CTAs/SM.
template<int BM, int BN, bool BKFAST, int EPI, bool ASRC16, bool ASPLIT,
         bool BSRC16, bool BSPLIT>
__global__ __launch_bounds__(256, 2)
void mma_gemm(const void* __restrict__ Ap, const void* __restrict__ Ap2,
              long long aBS, long long aRS,
              const void* __restrict__ Bp, long long bBS, long long bS,
              void* __restrict__ Cp, long long cBS, long long cRS,
              const void* __restrict__ Cin,
              const float* __restrict__ bias, float alpha,
              int K, float* __restrict__ Zp)
{
    constexpr int MT    = BM / 64;
    constexpr int NTL   = BN / 16;
    constexpr int NPAIR = NTL / 2;
    constexpr int ROWB  = 144;
    constexpr int STG   = (BM + BN) * ROWB;
    constexpr int AREG  = BM * 16 / 256;
    constexpr int BREG2 = BKFAST ? BN * 16 / 256 : 1;
    constexpr int BREG1 = BKFAST ? 1 : BN * 32 / 256;

    extern __shared__ __align__(16) char smem[];

    const int tid  = threadIdx.x;
    const int wid  = tid >> 5;
    const int lane = tid & 31;
    const int wm   = wid >> 1;
    const int wn   = wid & 1;
    const int mat  = lane >> 3;
    const int rw   = lane & 7;

    const int tile_n = blockIdx.x * BN;
    const int tile_m = blockIdx.y * BM;
    const int z      = blockIdx.z;

    const long long aOff = (long long)z * aBS + (long long)tile_m * aRS;
    const float*    AzF  = (const float*)Ap + aOff;
    const uint16_t* AzU  = (const uint16_t*)Ap + aOff;
    const uint16_t* AzU2 = (const uint16_t*)Ap2 + aOff;
    const float*    BzF  = (const float*)Bp + (long long)z * bBS;
    const uint16_t* BzU  = (const uint16_t*)Bp + (long long)z * bBS;

    float acc[MT][NTL][4];
#pragma unroll
    for (int i = 0; i < MT; i++)
#pragma unroll
        for (int j = 0; j < NTL; j++)
#pragma unroll
            for (int q = 0; q < 4; q++) acc[i][j][q] = 0.0f;

    const uint32_t s_u = smem_u32(smem);
    const uint32_t aAddr0 = s_u + (uint32_t)(wm * (BM / 4) + rw + (mat & 1) * 8) * ROWB
                                + (uint32_t)((mat >> 1) * 16);
    const uint32_t bAddr0 = s_u + (uint32_t)(BM * ROWB)
                                + (uint32_t)(wn * (BN / 2) + rw + (mat >> 1) * 8) * ROWB
                                + (uint32_t)((mat & 1) * 16);

    float2   aRegF[(!ASRC16) ? AREG : 1];
    uint32_t aRegH[ASRC16 ? AREG : 1];
    uint32_t aRegL[(ASRC16 && ASPLIT) ? AREG : 1];
    float2   bRegF[(BKFAST && !BSRC16) ? BREG2 : 1];
    uint32_t bRegH[(BKFAST && BSRC16) ? BREG2 : 1];
    float    bReg1[(!BKFAST && !BSRC16) ? BREG1 : 1];
    uint16_t bReg1U[(!BKFAST && BSRC16) ? BREG1 : 1];

    auto ldgA = [&](int ch) {
#pragma unroll
        for (int j = 0; j < AREG; j++) {
            int i = tid + j * 256;
            int k2 = i & 15, r = i >> 4;
            long long off = (long long)r * aRS + (ch << 5) + k2 * 2;
            if (ASRC16) {
                aRegH[j] = *reinterpret_cast<const uint32_t*>(AzU + off);
                if (ASPLIT)
                    aRegL[j] = *reinterpret_cast<const uint32_t*>(AzU2 + off);
            } else {
                aRegF[j] = *reinterpret_cast<const float2*>(AzF + off);
            }
        }
    };
    auto stsA = [&](int st) {
        char* base = smem + st * STG;
#pragma unroll
        for (int j = 0; j < AREG; j++) {
            int i = tid + j * 256;
            int k2 = i & 15, r = i >> 4;
            char* rp = base + r * ROWB + k2 * 4;
            if (ASRC16) {
                *reinterpret_cast<uint32_t*>(rp) = aRegH[j];
                if (ASPLIT) *reinterpret_cast<uint32_t*>(rp + 64) = aRegL[j];
            } else if (ASPLIT) {
                uint32_t hi, lo;
                split2h(aRegF[j].x, aRegF[j].y, hi, lo);
                *reinterpret_cast<uint32_t*>(rp)      = hi;
                *reinterpret_cast<uint32_t*>(rp + 64) = lo;
            } else {
                *reinterpret_cast<uint32_t*>(rp) = hi2h(aRegF[j].x, aRegF[j].y);
            }
        }
    };
    auto ldgB = [&](int ch) {
        if (BKFAST) {
#pragma unroll
            for (int j = 0; j < BREG2; j++) {
                int i = tid + j * 256;
                int k2 = i & 15, r = i >> 4;
                long long off = (long long)(tile_n + r) * bS + (ch << 5) + k2 * 2;
                if (BSRC16) bRegH[j] = *reinterpret_cast<const uint32_t*>(BzU + off);
                else        bRegF[j] = *reinterpret_cast<const float2*>(BzF + off);
            }
        } else {
#pragma unroll
            for (int j = 0; j < BREG1; j++) {
                int i = tid + j * 256;
                int n = i & (BN - 1), k = i / BN;
                long long off = (long long)((ch << 5) + k) * bS + tile_n + n;
                if (BSRC16) bReg1U[j] = BzU[off];
                else        bReg1[j]  = BzF[off];
            }
        }
    };
    auto stsB = [&](int st) {
        char* base = smem + st * STG + BM * ROWB;
        if (BKFAST) {
#pragma unroll
            for (int j = 0; j < BREG2; j++) {
                int i = tid + j * 256;
                int k2 = i & 15, r = i >> 4;
                char* rp = base + r * ROWB + k2 * 4;
                if (BSRC16) {
                    *reinterpret_cast<uint32_t*>(rp) = bRegH[j];
                } else if (BSPLIT) {
                    uint32_t hi, lo;
                    split2h(bRegF[j].x, bRegF[j].y, hi, lo);
                    *reinterpret_cast<uint32_t*>(rp)      = hi;
                    *reinterpret_cast<uint32_t*>(rp + 64) = lo;
                } else {
                    *reinterpret_cast<uint32_t*>(rp) = hi2h(bRegF[j].x, bRegF[j].y);
                }
            }
        } else {
#pragma unroll
            for (int j = 0; j < BREG1; j++) {
                int i = tid + j * 256;
                int n = i & (BN - 1), k = i / BN;
                char* rp = base + n * ROWB + k * 2;
                if (BSRC16) {
                    *reinterpret_cast<unsigned short*>(rp) = bReg1U[j];
                } else {
                    float v = bReg1[j];
                    __half hh = __float2half_rn(v);
                    *reinterpret_cast<unsigned short*>(rp) = __half_as_ushort(hh);
                    if (BSPLIT) {
                        __half ll = __float2half_rn(v - __half2float(hh));
                        *reinterpret_cast<unsigned short*>(rp + 64) = __half_as_ushort(ll);
                    }
                }
            }
        }
    };
    auto compute = [&](int st) {
        const uint32_t off = (uint32_t)(st * STG);
#pragma unroll
        for (int ks = 0; ks < 2; ks++) {
            uint32_t aH[MT][4], aL[MT][4];
#pragma unroll
            for (int mt = 0; mt < MT; mt++) {
                uint32_t ad = aAddr0 + off + (uint32_t)(mt * 16 * ROWB) + (uint32_t)(ks * 32);
                ldsm_x4(aH[mt], ad);
                if (ASPLIT) ldsm_x4(aL[mt], ad + 64);
            }
            uint32_t bH[NTL][2], bL[NTL][2];
#pragma unroll
            for (int p = 0; p < NPAIR; p++) {
                uint32_t bd = bAddr0 + off + (uint32_t)(p * 16 * ROWB) + (uint32_t)(ks * 32);
                uint32_t t[4];
                ldsm_x4(t, bd);
                bH[2 * p][0] = t[0]; bH[2 * p][1] = t[1];
                bH[2 * p + 1][0] = t[2]; bH[2 * p + 1][1] = t[3];
                if (BSPLIT) {
                    ldsm_x4(t, bd + 64);
                    bL[2 * p][0] = t[0]; bL[2 * p][1] = t[1];
                    bL[2 * p + 1][0] = t[2]; bL[2 * p + 1][1] = t[3];
                }
            }
#pragma unroll
            for (int mt = 0; mt < MT; mt++)
#pragma unroll
                for (int nt = 0; nt < NTL; nt++) {
                    mma_f16(acc[mt][nt], aH[mt], bH[nt]);
                    if (BSPLIT) mma_f16(acc[mt][nt], aH[mt], bL[nt]);
                    if (ASPLIT) mma_f16(acc[mt][nt], aL[mt], bH[nt]);
                }
        }
    };

    const int nch = K >> 5;
    ldgA(0); ldgB(0);
    stsA(0); stsB(0);
    __syncthreads();
    for (int ch = 0; ch < nch; ch++) {
        const bool more = (ch + 1 < nch);
        if (more) { ldgA(ch + 1); ldgB(ch + 1); }
        compute(ch & 1);
        if (more) {
            stsA((ch + 1) & 1); stsB((ch + 1) & 1);
            __syncthreads();
        }
    }

    // ---- epilogue ----
#pragma unroll
    for (int mt = 0; mt < MT; mt++) {
        int m0 = tile_m + wm * (BM / 4) + mt * 16 + (lane >> 2);
#pragma unroll
        for (int half = 0; half < 2; half++) {
            int m = m0 + half * 8;
            const long long coff = (long long)z * cBS + (long long)m * cRS;
            if (EPI == 6) {
                const __half* cinrow = (const __half*)Cin + coff;
                __half* erow = (__half*)Cp + coff;
                float rowsum = 0.0f;
#pragma unroll
                for (int nt = 0; nt < NTL; nt++) {
                    int n = tile_n + wn * (BN / 2) + nt * 8 + (lane & 3) * 2;
                    float2 o = __half22float2(*reinterpret_cast<const __half2*>(cinrow + n));
                    float ex = __expf(acc[mt][nt][half * 2]     + o.x);
                    float ey = __expf(acc[mt][nt][half * 2 + 1] + o.y);
                    *reinterpret_cast<__half2*>(erow + n) = __floats2half2_rn(ex, ey);
                    rowsum += ex + ey;
                }
                rowsum += __shfl_xor_sync(0xffffffffu, rowsum, 1);
                rowsum += __shfl_xor_sync(0xffffffffu, rowsum, 2);
                if ((lane & 3) == 0)
                    atomicAdd(&Zp[(long long)z * 1024 + m], rowsum);
            } else if (EPI == 7) {
                __half* crow = (__half*)Cp + coff;
#pragma unroll
                for (int nt = 0; nt < NTL; nt++) {
                    int n = tile_n + wn * (BN / 2) + nt * 8 + (lane & 3) * 2;
                    float vx = acc[mt][nt][half * 2];
                    float vy = acc[mt][nt][half * 2 + 1];
                    if (bias) { vx += bias[n]; vy += bias[n + 1]; }
                    vx *= alpha; vy *= alpha;
                    *reinterpret_cast<__half2*>(crow + n) = __floats2half2_rn(vx, vy);
                }
            } else if (EPI == 8) {
                const float* cinrow = (const float*)Cin + coff;
                __half* crow = (__half*)Cp + coff;
                float invZ = 1.0f / Zp[(long long)m * 1024 + z];
#pragma unroll
                for (int nt = 0; nt < NTL; nt++) {
                    int n = tile_n + wn * (BN / 2) + nt * 8 + (lane & 3) * 2;
                    float2 o = *reinterpret_cast<const float2*>(cinrow + n);
                    float vx = (acc[mt][nt][half * 2]     + o.x) * invZ;
                    float vy = (acc[mt][nt][half * 2 + 1] + o.y) * invZ;
                    *reinterpret_cast<__half2*>(crow + n) = __floats2half2_rn(vx, vy);
                }
            } else {
                float* crow = (float*)Cp + coff;
#pragma unroll
                for (int nt = 0; nt < NTL; nt++) {
                    int n = tile_n + wn * (BN / 2) + nt * 8 + (lane & 3) * 2;
                    float vx = acc[mt][nt][half * 2];
                    float vy = acc[mt][nt][half * 2 + 1];
                    if (bias) { vx += bias[n]; vy += bias[n + 1]; }
                    vx *= alpha; vy *= alpha;
                    float2 v; v.x = vx; v.y = vy;
                    *reinterpret_cast<float2*>(crow + n) = v;
                }
            }
        }
    }
}

// =================== small kernels ===========================================
__global__ __launch_bounds__(256)
void zeroZ_kernel(float* __restrict__ Z)
{
    Z[blockIdx.x * 256 + threadIdx.x] = 0.0f;
}

__global__ __launch_bounds__(256)
void avgw_kernel(const __half* __restrict__ Ebuf, const float* __restrict__ Z,
                 float* __restrict__ out)
{
    int l = blockIdx.x;
    int n = blockIdx.y;
    __shared__ float invZ[8];
    if (threadIdx.x < 8)
        invZ[threadIdx.x] = 0.125f / Z[(n * 8 + threadIdx.x) * 1024 + l];
    __syncthreads();
    int s = threadIdx.x * 4;
    float4 acc = make_float4(0.f, 0.f, 0.f, 0.f);
#pragma unroll
    for (int h = 0; h < 8; h++) {
        const __half2* p = reinterpret_cast<const __half2*>(
            Ebuf + (((long long)(n * 8 + h)) << 20) + (long long)l * 1024 + s);
        float2 a = __half22float2(p[0]);
        float2 b = __half22float2(p[1]);
        float w = invZ[h];
        acc.x += a.x * w; acc.y += a.y * w; acc.z += b.x * w; acc.w += b.y * w;
    }
    *reinterpret_cast<float4*>(
        out + (((long long)n) << 20) + (long long)l * 1024 + s) = acc;
}

// =================== launch ==================================================
extern "C" void kernel_launch(void* const* d_in, const int* in_sizes, int n_in,
                              void* d_out, int out_size)
{
    const float* query = (const float*)d_in[0];
    const float* key   = (const float*)d_in[1];
    const float* value = (const float*)d_in[2];
    const float* pos_k = (const float*)d_in[3];
    const float* pos_v = (const float*)d_in[4];
    const float* Wq = (const float*)d_in[5];
    const float* bq = (const float*)d_in[6];
    const float* Wk = (const float*)d_in[7];
    const float* bk = (const float*)d_in[8];
    const float* Wv = (const float*)d_in[9];
    const float* bv = (const float*)d_in[10];
    const float* Wo = (const float*)d_in[11];
    const float* bo = (const float*)d_in[12];
    float* out = (float*)d_out;

    __half *qp, *kp, *vp, *Pbuf, *Ebuf, *oph;
    float *Zbuf, *Obuf;
    cudaGetSymbolAddress((void**)&qp,    g_qp);
    cudaGetSymbolAddress((void**)&kp,    g_kp);
    cudaGetSymbolAddress((void**)&vp,    g_vp);
    cudaGetSymbolAddress((void**)&Pbuf,  g_P);
    cudaGetSymbolAddress((void**)&Ebuf,  g_E);
    cudaGetSymbolAddress((void**)&Zbuf,  g_Z);
    cudaGetSymbolAddress((void**)&Obuf,  g_O);
    cudaGetSymbolAddress((void**)&oph,   g_oph);

    const int SM_128_64  = 2 * (128 + 64) * 144;    // 55296
    const int SM_64_128  = 2 * (64 + 128) * 144;    // 55296
    const int SM_128_128 = 2 * (128 + 128) * 144;   // 73728
    const int SM_64_64   = 2 * (64 + 64) * 144;     // 36864

    // projections: fp32 A -> fp16 hi (1-term), W -> fp16 hi, fp16 out
    cudaFuncSetAttribute(
        (const void*)mma_gemm<128, 64, true, 7, false, false, false, false>,
        cudaFuncAttributeMaxDynamicSharedMemorySize, SM_128_64);
    // posk: A = qp fp16 (1-term), B = pos_k fp32->fp16 hi, fp16 P out
    cudaFuncSetAttribute(
        (const void*)mma_gemm<64, 128, true, 7, true, false, false, false>,
        cudaFuncAttributeMaxDynamicSharedMemorySize, SM_64_128);
    // scores: A = qp fp16 (1-term), B = kp fp16, BN=128, EXPZ
    cudaFuncSetAttribute(
        (const void*)mma_gemm<128, 128, true, 6, true, false, true, false>,
        cudaFuncAttributeMaxDynamicSharedMemorySize, SM_128_128);
    // contout: A = E fp16, B = vp fp16 n-contig (1-term), fp32 out
    cudaFuncSetAttribute(
        (const void*)mma_gemm<128, 64, false, 0, true, false, true, false>,
        cudaFuncAttributeMaxDynamicSharedMemorySize, SM_128_64);
    // posv: A = E fp16, B = pos_v fp32->fp16 hi n-contig (1-term), DIVZ fp16 out
    cudaFuncSetAttribute(
        (const void*)mma_gemm<64, 64, false, 8, true, false, false, false>,
        cudaFuncAttributeMaxDynamicSharedMemorySize, SM_64_64);
    // outproj: A = oph fp16 (1-term), B = Wo fp32->fp16 hi, fp32 out
    cudaFuncSetAttribute(
        (const void*)mma_gemm<128, 64, true, 0, true, false, false, false>,
        cudaFuncAttributeMaxDynamicSharedMemorySize, SM_128_64);

    // ---- side streams + events (created once, before any capture) ----
    static cudaStream_t sB = nullptr, sC = nullptr;
    static cudaEvent_t evStart, evB1, evC1, evScores, evAvgw;
    if (sB == nullptr) {
        cudaStreamCreateWithFlags(&sB, cudaStreamNonBlocking);
        cudaStreamCreateWithFlags(&sC, cudaStreamNonBlocking);
        cudaEventCreateWithFlags(&evStart,  cudaEventDisableTiming);
        cudaEventCreateWithFlags(&evB1,     cudaEventDisableTiming);
        cudaEventCreateWithFlags(&evC1,     cudaEventDisableTiming);
        cudaEventCreateWithFlags(&evScores, cudaEventDisableTiming);
        cudaEventCreateWithFlags(&evAvgw,   cudaEventDisableTiming);
    }

    // fork side streams from the (captured) main stream
    cudaEventRecord(evStart, 0);
    cudaStreamWaitEvent(sB, evStart, 0);
    cudaStreamWaitEvent(sC, evStart, 0);

    // --- stream B: zeroZ + proj k; later avgw ---
    zeroZ_kernel<<<256, 256, 0, sB>>>(Zbuf);
    mma_gemm<128, 64, true, 7, false, false, false, false>
        <<<dim3(8, 64, 1), 256, SM_128_64, sB>>>(
        key, nullptr, 0, 512,  Wk, 0, 512,
        kp, 0, 512,  nullptr, bk, 1.0f, 512, nullptr);
    cudaEventRecord(evB1, sB);

    // --- stream C: proj v ---
    mma_gemm<128, 64, true, 7, false, false, false, false>
        <<<dim3(8, 64, 1), 256, SM_128_64, sC>>>(
        value, nullptr, 0, 512,  Wv, 0, 512,
        vp, 0, 512,  nullptr, bv, 1.0f, 512, nullptr);
    cudaEventRecord(evC1, sC);

    // --- main: proj q -> posk ---
    mma_gemm<128, 64, true, 7, false, false, false, false>
        <<<dim3(8, 64, 1), 256, SM_128_64>>>(
        query, nullptr, 0, 512,  Wq, 0, 512,
        qp, 0, 512,  nullptr, bq, 0.125f, 512, nullptr);

    mma_gemm<64, 128, true, 7, true, false, false, false>
        <<<dim3(8, 1, 1024), 256, SM_64_128>>>(
        qp, nullptr, 4096, 64,  pos_k, 65536, 64,
        Pbuf, 1024, (long long)1 << 20,
        nullptr, nullptr, 1.0f, 64, nullptr);

    // --- main: scores (needs proj k + zeroZ from stream B), 1-term, BN=128 ---
    cudaStreamWaitEvent(0, evB1, 0);
    mma_gemm<128, 128, true, 6, true, false, true, false>
        <<<dim3(8, 8, 64), 256, SM_128_128>>>(
        qp, nullptr, 64, 4096,  kp, 64, 4096,
        Ebuf, (long long)1 << 20, 1024,
        Pbuf, nullptr, 1.0f, 64, Zbuf);
    cudaEventRecord(evScores, 0);

    // --- stream B: avgw (overlaps contout/posv/outproj) ---
    cudaStreamWaitEvent(sB, evScores, 0);
    avgw_kernel<<<dim3(1024, 8, 1), 256, 0, sB>>>(Ebuf, Zbuf, out + 4194304);
    cudaEventRecord(evAvgw, sB);

    // --- main: contout = E @ v -> O fp32 (needs proj v) ---
    cudaStreamWaitEvent(0, evC1, 0);
    mma_gemm<128, 64, false, 0, true, false, true, false>
        <<<dim3(1, 8, 64), 256, SM_128_64>>>(
        Ebuf, nullptr, (long long)1 << 20, 1024,  vp, 64, 4096,
        Obuf, 64, 4096,  nullptr, nullptr, 1.0f, 1024, nullptr);

    // --- main: posv + normalize -> fp16 oph ---
    mma_gemm<64, 64, false, 8, true, false, false, false>
        <<<dim3(1, 1, 1024), 256, SM_64_64>>>(
        Ebuf, nullptr, 1024, (long long)1 << 20,  pos_v, 65536, 64,
        oph, 4096, 64,  Obuf, nullptr, 1.0f, 1024, Zbuf);

    // --- main: output projection (1-term) ---
    mma_gemm<128, 64, true, 0, true, false, false, false>
        <<<dim3(8, 64, 1), 256, SM_128_64>>>(
        oph, nullptr, 0, 512,  Wo, 0, 512,
        out, 0, 512,  nullptr, bo, 1.0f, 512, nullptr);

    // join stream B (avgw) back into main before capture ends
    cudaStreamWaitEvent(0, evAvgw, 0);
}

// round 17
// speedup vs baseline: 1.2140x; 1.0623x over previous
#include <cuda_runtime.h>
#include <cuda_bf16.h>
#include <cuda_fp16.h>
#include <cstdint>

// Problem constants
#define LQ 1024
#define SQ 1024
#define NBATCH 8
#define EDIM 512
#define BHEADS 64   // NBATCH * HHEADS

// ---------------- scratch (device globals; no allocations allowed) ----------
__device__ __half g_qp[LQ * NBATCH * EDIM];         // q proj fp16
__device__ __half g_kp[SQ * NBATCH * EDIM];         // k proj fp16
__device__ __half g_vp[SQ * NBATCH * EDIM];         // v proj fp16
__device__ __half g_P[67108864];                    // pos-score term fp16 (b,l,s)
__device__ __half g_E[67108864];                    // exp scores fp16 (b,l,s)
__device__ float  g_Z[BHEADS * LQ];                 // row sums
__device__ float  g_O[LQ * NBATCH * EDIM];          // content numerator fp32 (l, b*64+d)
__device__ __half g_oph[LQ * NBATCH * EDIM];        // normalized O fp16

// =================== helpers ================================================
__device__ __forceinline__ uint32_t smem_u32(const void* p) {
    uint32_t a;
    asm("{ .reg .u64 t; cvta.to.shared.u64 t, %1; cvt.u32.u64 %0, t; }" : "=r"(a) : "l"(p));
    return a;
}
__device__ __forceinline__ void ldsm_x4(uint32_t* r, uint32_t addr) {
    asm volatile("ldmatrix.sync.aligned.m8n8.x4.shared.b16 {%0,%1,%2,%3}, [%4];"
        : "=r"(r[0]), "=r"(r[1]), "=r"(r[2]), "=r"(r[3]) : "r"(addr));
}
__device__ __forceinline__ void mma_f16(float* c, const uint32_t* a, const uint32_t* b) {
    asm volatile(
        "mma.sync.aligned.m16n8k16.row.col.f32.f16.f16.f32 "
        "{%0,%1,%2,%3}, {%4,%5,%6,%7}, {%8,%9}, {%0,%1,%2,%3};"
        : "+f"(c[0]), "+f"(c[1]), "+f"(c[2]), "+f"(c[3])
        : "r"(a[0]), "r"(a[1]), "r"(a[2]), "r"(a[3]), "r"(b[0]), "r"(b[1]));
}
__device__ __forceinline__ uint32_t hi2h(float x, float y) {
    __half2 h2 = __floats2half2_rn(x, y);
    return *reinterpret_cast<uint32_t*>(&h2);
}

// =================== HMMA strided batched GEMM (fp16, 1-term, BK=64) =========
// C[z][m][n] = epilogue( sum_k A(m,k)*B(n,k) )
// A(m,k): k contiguous. ASRC16 ? fp16 : fp32 (rounded to fp16)
// B: BKFAST (k contig): BSRC16 ? fp16 : fp32 (rounded)
//    !BKFAST (n contig): BSRC16 ? fp16 : fp32 (rounded)
// EPI: 0 = fp32 C = alpha*(acc+bias)
//      6 = EXPZ: e = exp(acc + CinH[..]); fp16 e -> Cp; atomicAdd Zp[z*1024+m]
//      7 = fp16 Cp = alpha*(acc+bias)
//      8 = DIVZ: fp16 Cp = (acc + CinF)/Zp[m*1024+z]
// 256 threads = 8 warps (4m x 2n). BK=64 (full 144B row used: 64 fp16/row).
// Double-buffered. 2 CTAs/SM.
template<int BM, int BN, bool BKFAST, int EPI, bool ASRC16, bool BSRC16>
__global__ __launch_bounds__(256, 2)
void mma_gemm(const void* __restrict__ Ap, long long aBS, long long aRS,
              const void* __restrict__ Bp, long long bBS, long long bS,
              void* __restrict__ Cp, long long cBS, long long cRS,
              const void* __restrict__ Cin,
              const float* __restrict__ bias, float alpha,
              int K, float* __restrict__ Zp)
{
    constexpr int MT    = BM / 64;
    constexpr int NTL   = BN / 16;
    constexpr int NPAIR = NTL / 2;
    constexpr int ROWB  = 144;
    constexpr int STG   = (BM + BN) * ROWB;
    constexpr int KW    = 32;                 // u32 slots per row (64 fp16)
    constexpr int AREG  = BM * KW / 256;      // u32/float2 loads per thread
    constexpr int BREG2 = BKFAST ? BN * KW / 256 : 1;
    constexpr int BREG1 = BKFAST ? 1 : BN * 64 / 256;

    extern __shared__ __align__(16) char smem[];

    const int tid  = threadIdx.x;
    const int wid  = tid >> 5;
    const int lane = tid & 31;
    const int wm   = wid >> 1;
    const int wn   = wid & 1;
    const int mat  = lane >> 3;
    const int rw   = lane & 7;

    const int tile_n = blockIdx.x * BN;
    const int tile_m = blockIdx.y * BM;
    const int z      = blockIdx.z;

    const long long aOff = (long long)z * aBS + (long long)tile_m * aRS;
    const float*    AzF  = (const float*)Ap + aOff;
    const uint16_t* AzU  = (const uint16_t*)Ap + aOff;
    const float*    BzF  = (const float*)Bp + (long long)z * bBS;
    const uint16_t* BzU  = (const uint16_t*)Bp + (long long)z * bBS;

    float acc[MT][NTL][4];
#pragma unroll
    for (int i = 0; i < MT; i++)
#pragma unroll
        for (int j = 0; j < NTL; j++)
#pragma unroll
            for (int q = 0; q < 4; q++) acc[i][j][q] = 0.0f;

    const uint32_t s_u = smem_u32(smem);
    const uint32_t aAddr0 = s_u + (uint32_t)(wm * (BM / 4) + rw + (mat & 1) * 8) * ROWB
                                + (uint32_t)((mat >> 1) * 16);
    const uint32_t bAddr0 = s_u + (uint32_t)(BM * ROWB)
                                + (uint32_t)(wn * (BN / 2) + rw + (mat >> 1) * 8) * ROWB
                                + (uint32_t)((mat & 1) * 16);

    float2   aRegF[(!ASRC16) ? AREG : 1];
    uint32_t aRegH[ASRC16 ? AREG : 1];
    float2   bRegF[(BKFAST && !BSRC16) ? BREG2 : 1];
    uint32_t bRegH[(BKFAST && BSRC16) ? BREG2 : 1];
    float    bReg1[(!BKFAST && !BSRC16) ? BREG1 : 1];
    uint16_t bReg1U[(!BKFAST && BSRC16) ? BREG1 : 1];

    auto ldgA = [&](int ch) {
#pragma unroll
        for (int j = 0; j < AREG; j++) {
            int i = tid + j * 256;
            int k2 = i & (KW - 1), r = i / KW;
            long long off = (long long)r * aRS + (ch << 6) + k2 * 2;
            if (ASRC16) aRegH[j] = *reinterpret_cast<const uint32_t*>(AzU + off);
            else        aRegF[j] = *reinterpret_cast<const float2*>(AzF + off);
        }
    };
    auto stsA = [&](int st) {
        char* base = smem + st * STG;
#pragma unroll
        for (int j = 0; j < AREG; j++) {
            int i = tid + j * 256;
            int k2 = i & (KW - 1), r = i / KW;
            char* rp = base + r * ROWB + k2 * 4;
            if (ASRC16) *reinterpret_cast<uint32_t*>(rp) = aRegH[j];
            else        *reinterpret_cast<uint32_t*>(rp) = hi2h(aRegF[j].x, aRegF[j].y);
        }
    };
    auto ldgB = [&](int ch) {
        if (BKFAST) {
#pragma unroll
            for (int j = 0; j < BREG2; j++) {
                int i = tid + j * 256;
                int k2 = i & (KW - 1), r = i / KW;
                long long off = (long long)(tile_n + r) * bS + (ch << 6) + k2 * 2;
                if (BSRC16) bRegH[j] = *reinterpret_cast<const uint32_t*>(BzU + off);
                else        bRegF[j] = *reinterpret_cast<const float2*>(BzF + off);
            }
        } else {
#pragma unroll
            for (int j = 0; j < BREG1; j++) {
                int i = tid + j * 256;
                int n = i & (BN - 1), k = i / BN;
                long long off = (long long)((ch << 6) + k) * bS + tile_n + n;
                if (BSRC16) bReg1U[j] = BzU[off];
                else        bReg1[j]  = BzF[off];
            }
        }
    };
    auto stsB = [&](int st) {
        char* base = smem + st * STG + BM * ROWB;
        if (BKFAST) {
#pragma unroll
            for (int j = 0; j < BREG2; j++) {
                int i = tid + j * 256;
                int k2 = i & (KW - 1), r = i / KW;
                char* rp = base + r * ROWB + k2 * 4;
                if (BSRC16) *reinterpret_cast<uint32_t*>(rp) = bRegH[j];
                else        *reinterpret_cast<uint32_t*>(rp) = hi2h(bRegF[j].x, bRegF[j].y);
            }
        } else {
#pragma unroll
            for (int j = 0; j < BREG1; j++) {
                int i = tid + j * 256;
                int n = i & (BN - 1), k = i / BN;
                char* rp = base + n * ROWB + k * 2;
                if (BSRC16) {
                    *reinterpret_cast<unsigned short*>(rp) = bReg1U[j];
                } else {
                    *reinterpret_cast<unsigned short*>(rp) =
                        __half_as_ushort(__float2half_rn(bReg1[j]));
                }
            }
        }
    };
    auto compute = [&](int st) {
        const uint32_t off = (uint32_t)(st * STG);
#pragma unroll
        for (int ks = 0; ks < 4; ks++) {
            uint32_t aH[MT][4];
#pragma unroll
            for (int mt = 0; mt < MT; mt++) {
                uint32_t ad = aAddr0 + off + (uint32_t)(mt * 16 * ROWB) + (uint32_t)(ks * 32);
                ldsm_x4(aH[mt], ad);
            }
            uint32_t bH[NTL][2];
#pragma unroll
            for (int p = 0; p < NPAIR; p++) {
                uint32_t bd = bAddr0 + off + (uint32_t)(p * 16 * ROWB) + (uint32_t)(ks * 32);
                uint32_t t[4];
                ldsm_x4(t, bd);
                bH[2 * p][0] = t[0]; bH[2 * p][1] = t[1];
                bH[2 * p + 1][0] = t[2]; bH[2 * p + 1][1] = t[3];
            }
#pragma unroll
            for (int mt = 0; mt < MT; mt++)
#pragma unroll
                for (int nt = 0; nt < NTL; nt++)
                    mma_f16(acc[mt][nt], aH[mt], bH[nt]);
        }
    };

    const int nch = K >> 6;
    ldgA(0); ldgB(0);
    stsA(0); stsB(0);
    __syncthreads();
    for (int ch = 0; ch < nch; ch++) {
        const bool more = (ch + 1 < nch);
        if (more) { ldgA(ch + 1); ldgB(ch + 1); }
        compute(ch & 1);
        if (more) {
            stsA((ch + 1) & 1); stsB((ch + 1) & 1);
            __syncthreads();
        }
    }

    // ---- epilogue ----
#pragma unroll
    for (int mt = 0; mt < MT; mt++) {
        int m0 = tile_m + wm * (BM / 4) + mt * 16 + (lane >> 2);
#pragma unroll
        for (int half = 0; half < 2; half++) {
            int m = m0 + half * 8;
            const long long coff = (long long)z * cBS + (long long)m * cRS;
            if (EPI == 6) {
                const __half* cinrow = (const __half*)Cin + coff;
                __half* erow = (__half*)Cp + coff;
                float rowsum = 0.0f;
#pragma unroll
                for (int nt = 0; nt < NTL; nt++) {
                    int n = tile_n + wn * (BN / 2) + nt * 8 + (lane & 3) * 2;
                    float2 o = __half22float2(*reinterpret_cast<const __half2*>(cinrow + n));
                    float ex = __expf(acc[mt][nt][half * 2]     + o.x);
                    float ey = __expf(acc[mt][nt][half * 2 + 1] + o.y);
                    *reinterpret_cast<__half2*>(erow + n) = __floats2half2_rn(ex, ey);
                    rowsum += ex + ey;
                }
                rowsum += __shfl_xor_sync(0xffffffffu, rowsum, 1);
                rowsum += __shfl_xor_sync(0xffffffffu, rowsum, 2);
                if ((lane & 3) == 0)
                    atomicAdd(&Zp[(long long)z * 1024 + m], rowsum);
            } else if (EPI == 7) {
                __half* crow = (__half*)Cp + coff;
#pragma unroll
                for (int nt = 0; nt < NTL; nt++) {
                    int n = tile_n + wn * (BN / 2) + nt * 8 + (lane & 3) * 2;
                    float vx = acc[mt][nt][half * 2];
                    float vy = acc[mt][nt][half * 2 + 1];
                    if (bias) { vx += bias[n]; vy += bias[n + 1]; }
                    vx *= alpha; vy *= alpha;
                    *reinterpret_cast<__half2*>(crow + n) = __floats2half2_rn(vx, vy);
                }
            } else if (EPI == 8) {
                const float* cinrow = (const float*)Cin + coff;
                __half* crow = (__half*)Cp + coff;
                float invZ = 1.0f / Zp[(long long)m * 1024 + z];
#pragma unroll
                for (int nt = 0; nt < NTL; nt++) {
                    int n = tile_n + wn * (BN / 2) + nt * 8 + (lane & 3) * 2;
                    float2 o = *reinterpret_cast<const float2*>(cinrow + n);
                    float vx = (acc[mt][nt][half * 2]     + o.x) * invZ;
                    float vy = (acc[mt][nt][half * 2 + 1] + o.y) * invZ;
                    *reinterpret_cast<__half2*>(crow + n) = __floats2half2_rn(vx, vy);
                }
            } else {
                float* crow = (float*)Cp + coff;
#pragma unroll
                for (int nt = 0; nt < NTL; nt++) {
                    int n = tile_n + wn * (BN / 2) + nt * 8 + (lane & 3) * 2;
                    float vx = acc[mt][nt][half * 2];
                    float vy = acc[mt][nt][half * 2 + 1];
                    if (bias) { vx += bias[n]; vy += bias[n + 1]; }
                    vx *= alpha; vy *= alpha;
                    float2 v; v.x = vx; v.y = vy;
                    *reinterpret_cast<float2*>(crow + n) = v;
                }
            }
        }
    }
}

// =================== small kernels ===========================================
__global__ __launch_bounds__(256)
void zeroZ_kernel(float* __restrict__ Z)
{
    Z[blockIdx.x * 256 + threadIdx.x] = 0.0f;
}

__global__ __launch_bounds__(256)
void avgw_kernel(const __half* __restrict__ Ebuf, const float* __restrict__ Z,
                 float* __restrict__ out)
{
    int l = blockIdx.x;
    int n = blockIdx.y;
    __shared__ float invZ[8];
    if (threadIdx.x < 8)
        invZ[threadIdx.x] = 0.125f / Z[(n * 8 + threadIdx.x) * 1024 + l];
    __syncthreads();
    int s = threadIdx.x * 4;
    float4 acc = make_float4(0.f, 0.f, 0.f, 0.f);
#pragma unroll
    for (int h = 0; h < 8; h++) {
        const __half2* p = reinterpret_cast<const __half2*>(
            Ebuf + (((long long)(n * 8 + h)) << 20) + (long long)l * 1024 + s);
        float2 a = __half22float2(p[0]);
        float2 b = __half22float2(p[1]);
        float w = invZ[h];
        acc.x += a.x * w; acc.y += a.y * w; acc.z += b.x * w; acc.w += b.y * w;
    }
    *reinterpret_cast<float4*>(
        out + (((long long)n) << 20) + (long long)l * 1024 + s) = acc;
}

// =================== launch ==================================================
extern "C" void kernel_launch(void* const* d_in, const int* in_sizes, int n_in,
                              void* d_out, int out_size)
{
    const float* query = (const float*)d_in[0];
    const float* key   = (const float*)d_in[1];
    const float* value = (const float*)d_in[2];
    const float* pos_k = (const float*)d_in[3];
    const float* pos_v = (const float*)d_in[4];
    const float* Wq = (const float*)d_in[5];
    const float* bq = (const float*)d_in[6];
    const float* Wk = (const float*)d_in[7];
    const float* bk = (const float*)d_in[8];
    const float* Wv = (const float*)d_in[9];
    const float* bv = (const float*)d_in[10];
    const float* Wo = (const float*)d_in[11];
    const float* bo = (const float*)d_in[12];
    float* out = (float*)d_out;

    __half *qp, *kp, *vp, *Pbuf, *Ebuf, *oph;
    float *Zbuf, *Obuf;
    cudaGetSymbolAddress((void**)&qp,    g_qp);
    cudaGetSymbolAddress((void**)&kp,    g_kp);
    cudaGetSymbolAddress((void**)&vp,    g_vp);
    cudaGetSymbolAddress((void**)&Pbuf,  g_P);
    cudaGetSymbolAddress((void**)&Ebuf,  g_E);
    cudaGetSymbolAddress((void**)&Zbuf,  g_Z);
    cudaGetSymbolAddress((void**)&Obuf,  g_O);
    cudaGetSymbolAddress((void**)&oph,   g_oph);

    const int SM_128_64  = 2 * (128 + 64) * 144;    // 55296
    const int SM_64_128  = 2 * (64 + 128) * 144;    // 55296
    const int SM_128_128 = 2 * (128 + 128) * 144;   // 73728
    const int SM_64_64   = 2 * (64 + 64) * 144;     // 36864

    // projections: fp32 A -> fp16, W fp32 -> fp16, fp16 out
    cudaFuncSetAttribute(
        (const void*)mma_gemm<128, 64, true, 7, false, false>,
        cudaFuncAttributeMaxDynamicSharedMemorySize, SM_128_64);
    // posk: A = qp fp16, B = pos_k fp32, fp16 P out
    cudaFuncSetAttribute(
        (const void*)mma_gemm<64, 128, true, 7, true, false>,
        cudaFuncAttributeMaxDynamicSharedMemorySize, SM_64_128);
    // scores: A = qp fp16, B = kp fp16, BN=128, EXPZ
    cudaFuncSetAttribute(
        (const void*)mma_gemm<128, 128, true, 6, true, true>,
        cudaFuncAttributeMaxDynamicSharedMemorySize, SM_128_128);
    // contout: A = E fp16, B = vp fp16 n-contig, fp32 out
    cudaFuncSetAttribute(
        (const void*)mma_gemm<128, 64, false, 0, true, true>,
        cudaFuncAttributeMaxDynamicSharedMemorySize, SM_128_64);
    // posv: A = E fp16, B = pos_v fp32 n-contig, DIVZ fp16 out
    cudaFuncSetAttribute(
        (const void*)mma_gemm<64, 64, false, 8, true, false>,
        cudaFuncAttributeMaxDynamicSharedMemorySize, SM_64_64);
    // outproj: A = oph fp16, B = Wo fp32, fp32 out
    cudaFuncSetAttribute(
        (const void*)mma_gemm<128, 64, true, 0, true, false>,
        cudaFuncAttributeMaxDynamicSharedMemorySize, SM_128_64);

    // ---- side streams + events (created once, before any capture) ----
    static cudaStream_t sB = nullptr, sC = nullptr;
    static cudaEvent_t evStart, evB1, evC1, evScores, evAvgw;
    if (sB == nullptr) {
        cudaStreamCreateWithFlags(&sB, cudaStreamNonBlocking);
        cudaStreamCreateWithFlags(&sC, cudaStreamNonBlocking);
        cudaEventCreateWithFlags(&evStart,  cudaEventDisableTiming);
        cudaEventCreateWithFlags(&evB1,     cudaEventDisableTiming);
        cudaEventCreateWithFlags(&evC1,     cudaEventDisableTiming);
        cudaEventCreateWithFlags(&evScores, cudaEventDisableTiming);
        cudaEventCreateWithFlags(&evAvgw,   cudaEventDisableTiming);
    }

    // fork side streams from the (captured) main stream
    cudaEventRecord(evStart, 0);
    cudaStreamWaitEvent(sB, evStart, 0);
    cudaStreamWaitEvent(sC, evStart, 0);

    // --- stream B: zeroZ + proj k; later avgw ---
    zeroZ_kernel<<<256, 256, 0, sB>>>(Zbuf);
    mma_gemm<128, 64, true, 7, false, false>
        <<<dim3(8, 64, 1), 256, SM_128_64, sB>>>(
        key, 0, 512,  Wk, 0, 512,
        kp, 0, 512,  nullptr, bk, 1.0f, 512, nullptr);
    cudaEventRecord(evB1, sB);

    // --- stream C: proj v ---
    mma_gemm<128, 64, true, 7, false, false>
        <<<dim3(8, 64, 1), 256, SM_128_64, sC>>>(
        value, 0, 512,  Wv, 0, 512,
        vp, 0, 512,  nullptr, bv, 1.0f, 512, nullptr);
    cudaEventRecord(evC1, sC);

    // --- main: proj q -> posk ---
    mma_gemm<128, 64, true, 7, false, false>
        <<<dim3(8, 64, 1), 256, SM_128_64>>>(
        query, 0, 512,  Wq, 0, 512,
        qp, 0, 512,  nullptr, bq, 0.125f, 512, nullptr);

    mma_gemm<64, 128, true, 7, true, false>
        <<<dim3(8, 1, 1024), 256, SM_64_128>>>(
        qp, 4096, 64,  pos_k, 65536, 64,
        Pbuf, 1024, (long long)1 << 20,
        nullptr, nullptr, 1.0f, 64, nullptr);

    // --- main: scores (needs proj k + zeroZ from stream B), BN=128 ---
    cudaStreamWaitEvent(0, evB1, 0);
    mma_gemm<128, 128, true, 6, true, true>
        <<<dim3(8, 8, 64), 256, SM_128_128>>>(
        qp, 64, 4096,  kp, 64, 4096,
        Ebuf, (long long)1 << 20, 1024,
        Pbuf, nullptr, 1.0f, 64, Zbuf);
    cudaEventRecord(evScores, 0);

    // --- stream B: avgw (overlaps contout/posv/outproj) ---
    cudaStreamWaitEvent(sB, evScores, 0);
    avgw_kernel<<<dim3(1024, 8, 1), 256, 0, sB>>>(Ebuf, Zbuf, out + 4194304);
    cudaEventRecord(evAvgw, sB);

    // --- main: contout = E @ v -> O fp32 (needs proj v) ---
    cudaStreamWaitEvent(0, evC1, 0);
    mma_gemm<128, 64, false, 0, true, true>
        <<<dim3(1, 8, 64), 256, SM_128_64>>>(
        Ebuf, (long long)1 << 20, 1024,  vp, 64, 4096,
        Obuf, 64, 4096,  nullptr, nullptr, 1.0f, 1024, nullptr);

    // --- main: posv + normalize -> fp16 oph ---
    mma_gemm<64, 64, false, 8, true, false>
        <<<dim3(1, 1, 1024), 256, SM_64_64>>>(
        Ebuf, 1024, (long long)1 << 20,  pos_v, 65536, 64,
        oph, 4096, 64,  Obuf, nullptr, 1.0f, 1024, Zbuf);

    // --- main: output projection ---
    mma_gemm<128, 64, true, 0, true, false>
        <<<dim3(8, 64, 1), 256, SM_128_64>>>(
        oph, 0, 512,  Wo, 0, 512,
        out, 0, 512,  nullptr, bo, 1.0f, 512, nullptr);

    // join stream B (avgw) back into main before capture ends
    cudaStreamWaitEvent(0, evAvgw, 0);
}